// round 12
// baseline (speedup 1.0000x reference)
#include <cuda_runtime.h>
#include <cuda_bf16.h>
#include <mma.h>
#include <cstdint>

using namespace nvcuda;

#define B_  8
#define N_  8192
#define H_  256
#define KD_ 260            // H + 4
#define KP_ 288            // K padded to 9*32
#define NU_ 2048
#define ND_ 6144
#define M_  5
#define EPG (ND_*M_)       // edges per graph = 30720
#define KSL 8              // KNN candidate slices
#define NSL (NU_/KSL)      // 256 candidates per slice
#define BM2 128            // GEMM M tile
#define GT_ 512            // GEMM threads
#define LDA2 40
#define LDB2 264
#define GA_HI(s) ((s)*10240)
#define GA_LO(s) (20480 + (s)*10240)
#define GB_HI(s) (40960 + (s)*16896)
#define GB_LO(s) (74752 + (s)*16896)
#define SMEM_G 108544

// ---------------- device scratch ----------------
__device__ int  g_up_idx[B_*NU_];
__device__ int  g_down_idx[B_*ND_];
__device__ int  g_dst[B_*ND_*M_];
__device__ unsigned char g_isup[B_*N_];
__device__ int  g_deg[B_*N_];
__device__ int  g_off[B_*N_];
__device__ int  g_cur[B_*N_];
__device__ int  g_src[B_*ND_*M_];
__device__ float g_feat[(size_t)B_*ND_*H_];
__device__ __nv_bfloat16 g_Whi[KP_*H_];
__device__ __nv_bfloat16 g_Wlo[KP_*H_];
__device__ float g_pd[(size_t)B_*ND_*KSL*M_];
__device__ int   g_pi[(size_t)B_*ND_*KSL*M_];

__device__ __forceinline__ unsigned enc_f(float f){
    unsigned u = __float_as_uint(f);
    return (u & 0x80000000u) ? ~u : (u | 0x80000000u);
}
__device__ __forceinline__ void cpa16(void* dst, const void* src){
    unsigned d = (unsigned)__cvta_generic_to_shared(dst);
    asm volatile("cp.async.cg.shared.global [%0], [%1], 16;" :: "r"(d), "l"(src));
}

// packed f32x2 helpers (sm_100+; per-lane rounding == scalar fp32)
__device__ __forceinline__ unsigned long long f2_pack(float lo, float hi){
    unsigned long long r;
    asm("mov.b64 %0, {%1, %2};" : "=l"(r) : "f"(lo), "f"(hi));
    return r;
}
__device__ __forceinline__ void f2_unpack(float& lo, float& hi, unsigned long long v){
    asm("mov.b64 {%0, %1}, %2;" : "=f"(lo), "=f"(hi) : "l"(v));
}
__device__ __forceinline__ unsigned long long f2_add(unsigned long long a, unsigned long long b){
    unsigned long long r;
    asm("add.rn.f32x2 %0, %1, %2;" : "=l"(r) : "l"(a), "l"(b));
    return r;
}
__device__ __forceinline__ unsigned long long f2_mul(unsigned long long a, unsigned long long b){
    unsigned long long r;
    asm("mul.rn.f32x2 %0, %1, %2;" : "=l"(r) : "l"(a), "l"(b));
    return r;
}
__device__ __forceinline__ unsigned long long f2_fma(unsigned long long a, unsigned long long b,
                                                     unsigned long long c){
    unsigned long long r;
    asm("fma.rn.f32x2 %0, %1, %2, %3;" : "=l"(r) : "l"(a), "l"(b), "l"(c));
    return r;
}

__device__ __forceinline__ int block_scan_excl(int val, int* s_warp, int tid){
    const int lane = tid & 31, wid = tid >> 5;
    int inc = val;
#pragma unroll
    for (int o = 1; o < 32; o <<= 1){
        int v = __shfl_up_sync(0xFFFFFFFFu, inc, o);
        if (lane >= o) inc += v;
    }
    if (lane == 31) s_warp[wid] = inc;
    __syncthreads();
    if (wid == 0){
        int w = (lane < 32) ? s_warp[lane] : 0;
#pragma unroll
        for (int o = 1; o < 32; o <<= 1){
            int v = __shfl_up_sync(0xFFFFFFFFu, w, o);
            if (lane >= o) w += v;
        }
        s_warp[lane] = w;
    }
    __syncthreads();
    int base = (wid > 0) ? s_warp[wid - 1] : 0;
    return base + inc - val;
}

// ---------------- K0: W split into hi/lo bf16 ----------------
__global__ void k_wsplit(const float* __restrict__ W){
    const int idx = blockIdx.x * 256 + threadIdx.x;
    if (idx >= KP_ * H_) return;
    const int k = idx / H_, n = idx % H_;
    const float w = (k < KD_) ? W[k * H_ + n] : 0.0f;
    const __nv_bfloat16 hi = __float2bfloat16(w);
    const __nv_bfloat16 lo = __float2bfloat16(w - __bfloat162float(hi));
    g_Whi[idx] = hi;
    g_Wlo[idx] = lo;
}

// ---------------- K1: top-25% selection ----------------
__global__ void k_select(const float* __restrict__ scores,
                         float* __restrict__ d_out, long long out_size){
    __shared__ unsigned s_enc[N_];
    __shared__ int s_warp[32];
    __shared__ int s_hist[256];
    __shared__ int s_bcast[2];
    const int b = blockIdx.x, tid = threadIdx.x;

    for (int i = tid; i < N_; i += 1024) g_deg[b * N_ + i] = 0;

    const float* sc = scores + (long long)b * N_;
    for (int i = tid; i < N_; i += 1024) s_enc[i] = enc_f(sc[i]);
    __syncthreads();

    unsigned prefix = 0, known = 0;
    int k = NU_;
    for (int lvl = 3; lvl >= 0; --lvl){
        if (tid < 256) s_hist[tid] = 0;
        __syncthreads();
        const int sh = lvl * 8;
        for (int i = tid; i < N_; i += 1024){
            unsigned e = s_enc[i];
            if ((e & known) == prefix) atomicAdd(&s_hist[(e >> sh) & 255], 1);
        }
        __syncthreads();
        if (tid == 0){
            int kk = k, bin = 255;
            while (bin > 0 && kk > s_hist[bin]) { kk -= s_hist[bin]; --bin; }
            s_bcast[0] = bin; s_bcast[1] = kk;
        }
        __syncthreads();
        prefix |= ((unsigned)s_bcast[0]) << sh;
        known  |= 0xFFu << sh;
        k = s_bcast[1];
        __syncthreads();
    }
    const unsigned T = prefix;

    if (tid == 0) s_bcast[0] = 0;
    __syncthreads();
    {
        int loc = 0;
        for (int i = tid; i < N_; i += 1024) if (s_enc[i] > T) loc++;
        atomicAdd(&s_bcast[0], loc);
    }
    __syncthreads();
    const int need_eq = NU_ - s_bcast[0];
    __syncthreads();

    const int base = tid * 8;
    int eqc = 0;
#pragma unroll
    for (int e = 0; e < 8; ++e) eqc += (s_enc[base + e] == T);
    int eqbase = block_scan_excl(eqc, s_warp, tid);
    __syncthreads();

    unsigned mbits = 0; int upc = 0;
    {
        int ec = eqbase;
#pragma unroll
        for (int e = 0; e < 8; ++e){
            unsigned v = s_enc[base + e];
            bool msk;
            if (v > T) msk = true;
            else if (v == T) { msk = (ec < need_eq); ec++; }
            else msk = false;
            if (msk) { mbits |= (1u << e); upc++; }
        }
    }
    int upbase = block_scan_excl(upc, s_warp, tid);

    const long long BNH = (long long)B_ * N_ * H_;
    const bool wf = (out_size == BNH + (long long)B_ * N_);
    const bool wb = (out_size == BNH + ((long long)B_ * N_) / 4);
    int up = upbase;
#pragma unroll
    for (int e = 0; e < 8; ++e){
        const int i = base + e;
        const bool msk = (mbits >> e) & 1;
        if (msk) { g_up_idx[b * NU_ + up] = i; up++; }
        else       g_down_idx[b * ND_ + (i - up)] = i;
        g_isup[b * N_ + i] = msk ? 1 : 0;
        if (wf)      d_out[BNH + (long long)b * N_ + i] = msk ? 1.0f : 0.0f;
        else if (wb) ((unsigned char*)d_out)[BNH * 4 + (long long)b * N_ + i] = msk ? 1 : 0;
    }
}

// -------- K2a: KNN phase 1 — f32x2 direct-load + batch-4 min guard --------
struct Top5 { float d0,d1,d2,d3,d4; int i0,i1,i2,i3,i4; };
__device__ __forceinline__ void top5_init(Top5& t){
    const float INF = __int_as_float(0x7f800000);
    t.d0=t.d1=t.d2=t.d3=t.d4=INF; t.i0=t.i1=t.i2=t.i3=t.i4=0;
}
__device__ __forceinline__ void top5_ins(Top5& t, float d, int j){
    if (d < t.d4){
        if (d < t.d3){ t.d4=t.d3; t.i4=t.i3;
            if (d < t.d2){ t.d3=t.d2; t.i3=t.i2;
                if (d < t.d1){ t.d2=t.d1; t.i2=t.i1;
                    if (d < t.d0){ t.d1=t.d0; t.i1=t.i0; t.d0=d; t.i0=j; }
                    else        { t.d1=d;  t.i1=j; }
                } else { t.d2=d; t.i2=j; }
            } else { t.d3=d; t.i3=j; }
        } else { t.d4=d; t.i4=j; }
    }
}

__global__ void k_knn_part(const float* __restrict__ s_l){
    // candidate j in packed-pair form: sxy[j] = {(x,x),(y,y)}, szz[j] = (z,z)
    __shared__ ulonglong2 sxy[NSL];
    __shared__ unsigned long long szz[NSL];
    __shared__ int sui[NSL];
    const int b  = blockIdx.y;
    const int sl = blockIdx.z;
    const int tid = threadIdx.x;
    for (int j = tid; j < NSL; j += 256){
        int u = g_up_idx[b * NU_ + sl * NSL + j];
        long long p = ((long long)b * N_ + u) * 3;
        float x = s_l[p], y = s_l[p+1], z = s_l[p+2];
        sxy[j].x = f2_pack(x, x);
        sxy[j].y = f2_pack(y, y);
        szz[j]   = f2_pack(z, z);
        sui[j]   = b * N_ + u;
    }
    __syncthreads();

    const int dlA = blockIdx.x * 512 + tid;   // grid.x = ND/512
    const int dlB = dlA + 256;
    const int dnA = g_down_idx[b * ND_ + dlA];
    const int dnB = g_down_idx[b * ND_ + dlB];
    long long pA = ((long long)b * N_ + dnA) * 3;
    long long pB = ((long long)b * N_ + dnB) * 3;
    // packed negated coords (A in lo lane, B in hi lane); (u-x)^2 == (x-u)^2
    const unsigned long long nx = f2_pack(-s_l[pA],   -s_l[pB]);
    const unsigned long long ny = f2_pack(-s_l[pA+1], -s_l[pB+1]);
    const unsigned long long nz = f2_pack(-s_l[pA+2], -s_l[pB+2]);

    Top5 tA, tB; top5_init(tA); top5_init(tB);
#pragma unroll 1
    for (int j = 0; j < NSL; j += 4){
        const ulonglong2 q0 = sxy[j],   q1 = sxy[j+1];
        const ulonglong2 q2 = sxy[j+2], q3 = sxy[j+3];
        const unsigned long long z0 = szz[j],   z1 = szz[j+1];
        const unsigned long long z2 = szz[j+2], z3 = szz[j+3];

        unsigned long long dx0 = f2_add(q0.x, nx), dy0 = f2_add(q0.y, ny), dz0 = f2_add(z0, nz);
        unsigned long long dx1 = f2_add(q1.x, nx), dy1 = f2_add(q1.y, ny), dz1 = f2_add(z1, nz);
        unsigned long long dx2 = f2_add(q2.x, nx), dy2 = f2_add(q2.y, ny), dz2 = f2_add(z2, nz);
        unsigned long long dx3 = f2_add(q3.x, nx), dy3 = f2_add(q3.y, ny), dz3 = f2_add(z3, nz);

        unsigned long long dd0 = f2_mul(dx0, dx0);
        unsigned long long dd1 = f2_mul(dx1, dx1);
        unsigned long long dd2 = f2_mul(dx2, dx2);
        unsigned long long dd3 = f2_mul(dx3, dx3);
        dd0 = f2_fma(dy0, dy0, dd0); dd1 = f2_fma(dy1, dy1, dd1);
        dd2 = f2_fma(dy2, dy2, dd2); dd3 = f2_fma(dy3, dy3, dd3);
        dd0 = f2_fma(dz0, dz0, dd0); dd1 = f2_fma(dz1, dz1, dd1);
        dd2 = f2_fma(dz2, dz2, dd2); dd3 = f2_fma(dz3, dz3, dd3);

        float a0, b0, a1, b1, a2, b2, a3, b3;
        f2_unpack(a0, b0, dd0); f2_unpack(a1, b1, dd1);
        f2_unpack(a2, b2, dd2); f2_unpack(a3, b3, dd3);

        const float mA = fminf(fminf(a0, a1), fminf(a2, a3));
        const float mB = fminf(fminf(b0, b1), fminf(b2, b3));
        // rare path: only if some candidate can enter the top-5; sequential
        // ascending-j inserts keep exact lax.top_k tie semantics.
        if (mA < tA.d4){
            top5_ins(tA, a0, j);   top5_ins(tA, a1, j+1);
            top5_ins(tA, a2, j+2); top5_ins(tA, a3, j+3);
        }
        if (mB < tB.d4){
            top5_ins(tB, b0, j);   top5_ins(tB, b1, j+1);
            top5_ins(tB, b2, j+2); top5_ins(tB, b3, j+3);
        }
    }

    {
        const size_t base = (((size_t)b * ND_ + dlA) * KSL + sl) * M_;
        g_pd[base+0]=tA.d0; g_pd[base+1]=tA.d1; g_pd[base+2]=tA.d2;
        g_pd[base+3]=tA.d3; g_pd[base+4]=tA.d4;
        g_pi[base+0]=sui[tA.i0]; g_pi[base+1]=sui[tA.i1]; g_pi[base+2]=sui[tA.i2];
        g_pi[base+3]=sui[tA.i3]; g_pi[base+4]=sui[tA.i4];
    }
    {
        const size_t base = (((size_t)b * ND_ + dlB) * KSL + sl) * M_;
        g_pd[base+0]=tB.d0; g_pd[base+1]=tB.d1; g_pd[base+2]=tB.d2;
        g_pd[base+3]=tB.d3; g_pd[base+4]=tB.d4;
        g_pi[base+0]=sui[tB.i0]; g_pi[base+1]=sui[tB.i1]; g_pi[base+2]=sui[tB.i2];
        g_pi[base+3]=sui[tB.i3]; g_pi[base+4]=sui[tB.i4];
    }
}

// -------- K2b: KNN phase 2 — 8-way merge of sorted 5-lists + degrees --------
__global__ void k_knn_merge(){
    const int pt = blockIdx.x * 256 + threadIdx.x;
    if (pt >= B_ * ND_) return;
    const size_t b0 = (size_t)pt * KSL * M_;
    float ld[KSL][5]; int li[KSL][5];
#pragma unroll
    for (int s = 0; s < KSL; ++s)
#pragma unroll
        for (int q = 0; q < 5; ++q){
            ld[s][q] = g_pd[b0 + s*5 + q];
            li[s][q] = g_pi[b0 + s*5 + q];
        }
    int hp[KSL];
#pragma unroll
    for (int s = 0; s < KSL; ++s) hp[s] = 0;
    int* dst = g_dst + (size_t)pt * M_;
    const float INF = __int_as_float(0x7f800000);
#pragma unroll
    for (int k = 0; k < 5; ++k){
        int bs = 0; float bd = INF;
#pragma unroll
        for (int s = 0; s < KSL; ++s){
            float v = (hp[s] < 5) ? ld[s][hp[s]] : INF;
            if (v < bd){ bd = v; bs = s; }
        }
        int e = li[bs][hp[bs]];
        hp[bs]++;
        dst[k] = e;
        atomicAdd(&g_deg[e], 1);
    }
}

// -------- K3: per-graph exclusive scan --------
__global__ void k_scan(){
    __shared__ int s_warp[32];
    const int b = blockIdx.x, tid = threadIdx.x;
    const int base = b * N_ + tid * 8;
    int d[8]; int s = 0;
#pragma unroll
    for (int i = 0; i < 8; ++i){ d[i] = g_deg[base + i]; s += d[i]; }
    int run = block_scan_excl(s, s_warp, tid) + b * EPG;
#pragma unroll
    for (int i = 0; i < 8; ++i){
        g_off[base + i] = run;
        g_cur[base + i] = run;
        run += d[i];
    }
}

// ---------------- K4: CSR fill ----------------
__global__ void k_fill(){
    const int e = blockIdx.x * 256 + threadIdx.x;
    if (e >= B_ * ND_ * M_) return;
    const int dst = g_dst[e];
    const int pos = atomicAdd(&g_cur[dst], 1);
    g_src[pos] = e / M_;
}

// -------- K5: pipelined WMMA bf16 hi/lo GEMM, BM=128 x BN=256, 512 thr ------
__device__ __forceinline__ void loadA_regs(float* xs, const float* __restrict__ hh,
                                           const float* __restrict__ sl,
                                           const float* __restrict__ sc,
                                           int g, int c, int ah){
    if (c < 8){
        const float4* hp = (const float4*)(hh + (size_t)g * H_ + c * 32 + ah);
        float4 f0 = hp[0], f1 = hp[1];
        xs[0]=f0.x; xs[1]=f0.y; xs[2]=f0.z; xs[3]=f0.w;
        xs[4]=f1.x; xs[5]=f1.y; xs[6]=f1.z; xs[7]=f1.w;
    } else {
#pragma unroll
        for (int q = 0; q < 8; ++q) xs[q] = 0.0f;
        if (ah == 0){
            xs[0] = sl[(size_t)g * 3];
            xs[1] = sl[(size_t)g * 3 + 1];
            xs[2] = sl[(size_t)g * 3 + 2];
            xs[3] = sc[g];
        }
    }
}

__global__ void __launch_bounds__(GT_, 1)
k_gemm_tc(const float* __restrict__ hh, const float* __restrict__ sl,
          const float* __restrict__ sc){
    extern __shared__ char sm[];
    __shared__ int s_g[BM2];

    const int b   = blockIdx.y;
    const int m0  = blockIdx.x * BM2;
    const int tid = threadIdx.x;
    const int w   = tid >> 5;
    const int wm  = w >> 2;
    const int wn  = w & 3;

    if (tid < BM2) s_g[tid] = b * N_ + g_down_idx[b * ND_ + m0 + tid];
    __syncthreads();

    const int ar = tid >> 2;
    const int ah = (tid & 3) * 8;
    const int g  = s_g[ar];

    wmma::fragment<wmma::accumulator, 16, 16, 16, float> acc[2][4];
#pragma unroll
    for (int i = 0; i < 2; ++i)
#pragma unroll
        for (int j = 0; j < 4; ++j) wmma::fill_fragment(acc[i][j], 0.0f);

    auto copyB = [&](int c, int s){
        const int k0 = c * 32;
        __nv_bfloat16* Bh = (__nv_bfloat16*)(sm + GB_HI(s));
        __nv_bfloat16* Bl = (__nv_bfloat16*)(sm + GB_LO(s));
#pragma unroll
        for (int q = 0; q < 2; ++q){
            const int i = tid + q * GT_;
            const int row = i >> 5;
            const int col = (i & 31) * 8;
            cpa16(Bh + row * LDB2 + col, g_Whi + (size_t)(k0 + row) * H_ + col);
            cpa16(Bl + row * LDB2 + col, g_Wlo + (size_t)(k0 + row) * H_ + col);
        }
        asm volatile("cp.async.commit_group;");
    };
    auto storeA = [&](const float* xs, int s){
        unsigned hw[4], lw[4];
#pragma unroll
        for (int q = 0; q < 4; ++q){
            __nv_bfloat16 h0 = __float2bfloat16(xs[2*q]);
            __nv_bfloat16 h1 = __float2bfloat16(xs[2*q+1]);
            __nv_bfloat16 l0 = __float2bfloat16(xs[2*q]   - __bfloat162float(h0));
            __nv_bfloat16 l1 = __float2bfloat16(xs[2*q+1] - __bfloat162float(h1));
            __nv_bfloat162 hp2 = __nv_bfloat162(h0, h1);
            __nv_bfloat162 lp2 = __nv_bfloat162(l0, l1);
            hw[q] = *(unsigned*)&hp2;
            lw[q] = *(unsigned*)&lp2;
        }
        *(uint4*)((__nv_bfloat16*)(sm + GA_HI(s)) + ar * LDA2 + ah) =
            make_uint4(hw[0], hw[1], hw[2], hw[3]);
        *(uint4*)((__nv_bfloat16*)(sm + GA_LO(s)) + ar * LDA2 + ah) =
            make_uint4(lw[0], lw[1], lw[2], lw[3]);
    };

    float xs[8], xs2[8];
    loadA_regs(xs, hh, sl, sc, g, 0, ah);
    copyB(0, 0);

    for (int c = 0; c < 9; ++c){
        const int s = c & 1;
        if (c < 8){
            loadA_regs(xs2, hh, sl, sc, g, c + 1, ah);
            copyB(c + 1, s ^ 1);
        }
        storeA(xs, s);
        if (c < 8) asm volatile("cp.async.wait_group 1;");
        else       asm volatile("cp.async.wait_group 0;");
        __syncthreads();

        const __nv_bfloat16* Ah = (const __nv_bfloat16*)(sm + GA_HI(s));
        const __nv_bfloat16* Al = (const __nv_bfloat16*)(sm + GA_LO(s));
        const __nv_bfloat16* Bh = (const __nv_bfloat16*)(sm + GB_HI(s));
        const __nv_bfloat16* Bl = (const __nv_bfloat16*)(sm + GB_LO(s));
#pragma unroll
        for (int kt = 0; kt < 2; ++kt){
            const int ks = kt * 16;
            wmma::fragment<wmma::matrix_a, 16, 16, 16, __nv_bfloat16, wmma::row_major> fa_hi[2], fa_lo[2];
#pragma unroll
            for (int i = 0; i < 2; ++i){
                wmma::load_matrix_sync(fa_hi[i], Ah + (wm*32 + i*16) * LDA2 + ks, LDA2);
                wmma::load_matrix_sync(fa_lo[i], Al + (wm*32 + i*16) * LDA2 + ks, LDA2);
            }
#pragma unroll
            for (int j = 0; j < 4; ++j){
                wmma::fragment<wmma::matrix_b, 16, 16, 16, __nv_bfloat16, wmma::row_major> fb_hi, fb_lo;
                wmma::load_matrix_sync(fb_hi, Bh + ks * LDB2 + wn*64 + j*16, LDB2);
                wmma::load_matrix_sync(fb_lo, Bl + ks * LDB2 + wn*64 + j*16, LDB2);
#pragma unroll
                for (int i = 0; i < 2; ++i){
                    wmma::mma_sync(acc[i][j], fa_hi[i], fb_hi, acc[i][j]);
                    wmma::mma_sync(acc[i][j], fa_hi[i], fb_lo, acc[i][j]);
                    wmma::mma_sync(acc[i][j], fa_lo[i], fb_hi, acc[i][j]);
                }
            }
        }
        __syncthreads();
#pragma unroll
        for (int q = 0; q < 8; ++q) xs[q] = xs2[q];
    }

#pragma unroll
    for (int i = 0; i < 2; ++i){
        const int row = m0 + wm * 32 + i * 16;
#pragma unroll
        for (int j = 0; j < 4; ++j){
            const int col = wn * 64 + j * 16;
            wmma::store_matrix_sync(
                g_feat + ((size_t)b * ND_ + row) * H_ + col,
                acc[i][j], H_, wmma::mem_row_major);
        }
    }
}

// ---------------- K6: gather-max (+bias) into output ----------------
__global__ void k_gather(float* __restrict__ out, const float* __restrict__ bias){
    const int wid = threadIdx.x >> 5, lane = threadIdx.x & 31;
    const int row = blockIdx.x * 8 + wid;
    float* op = out + (size_t)row * H_;
    const int c0 = lane * 4;
    const float4 z = make_float4(0.f, 0.f, 0.f, 0.f);
    const int deg = g_deg[row];
    if (!g_isup[row] || deg == 0){
        *(float4*)(op + c0) = z;
        *(float4*)(op + c0 + 128) = z;
        return;
    }
    const int off = g_off[row];
    const float NI = __int_as_float(0xff800000);
    float4 a = make_float4(NI, NI, NI, NI), bq = a;
    for (int e = 0; e < deg; ++e){
        const float* fp = g_feat + (size_t)g_src[off + e] * H_;
        float4 u = *(const float4*)(fp + c0);
        float4 v = *(const float4*)(fp + c0 + 128);
        a.x = fmaxf(a.x, u.x); a.y = fmaxf(a.y, u.y);
        a.z = fmaxf(a.z, u.z); a.w = fmaxf(a.w, u.w);
        bq.x = fmaxf(bq.x, v.x); bq.y = fmaxf(bq.y, v.y);
        bq.z = fmaxf(bq.z, v.z); bq.w = fmaxf(bq.w, v.w);
    }
    const float4 ba = *(const float4*)(bias + c0);
    const float4 bb = *(const float4*)(bias + c0 + 128);
    a.x += ba.x; a.y += ba.y; a.z += ba.z; a.w += ba.w;
    bq.x += bb.x; bq.y += bb.y; bq.z += bb.z; bq.w += bb.w;
    *(float4*)(op + c0) = a;
    *(float4*)(op + c0 + 128) = bq;
}

// ------------------------------- launch ------------------------------------
extern "C" void kernel_launch(void* const* d_in, const int* in_sizes, int n_in,
                              void* d_out, int out_size){
    const float* hh = (const float*)d_in[0];
    const float* sl = (const float*)d_in[1];
    const float* sc = (const float*)d_in[2];
    const float* W  = (const float*)d_in[3];
    const float* bb = (const float*)d_in[4];
    (void)in_sizes; (void)n_in;

    cudaFuncSetAttribute(k_gemm_tc, cudaFuncAttributeMaxDynamicSharedMemorySize, SMEM_G);

    k_wsplit<<<(KP_*H_ + 255)/256, 256>>>(W);                       // 0
    k_select<<<B_, 1024>>>(sc, (float*)d_out, (long long)out_size); // 1
    dim3 gg(ND_ / BM2, B_);
    k_gemm_tc<<<gg, GT_, SMEM_G>>>(hh, sl, sc);                     // 2
    dim3 gknn(ND_ / 512, B_, KSL);
    k_knn_part<<<gknn, 256>>>(sl);                                   // 3 (profiled)
    k_knn_merge<<<(B_*ND_ + 255)/256, 256>>>();                      // 4
    k_scan<<<B_, 1024>>>();                                          // 5
    k_fill<<<(B_*ND_*M_ + 255)/256, 256>>>();                        // 6
    k_gather<<<B_*N_/8, 256>>>((float*)d_out, bb);                   // 7
}

// round 13
// speedup vs baseline: 1.0295x; 1.0295x over previous
#include <cuda_runtime.h>
#include <cuda_bf16.h>
#include <mma.h>
#include <cstdint>

using namespace nvcuda;

#define B_  8
#define N_  8192
#define H_  256
#define KD_ 260            // H + 4
#define KP_ 288            // K padded to 9*32
#define NU_ 2048
#define ND_ 6144
#define M_  5
#define EPG (ND_*M_)       // edges per graph = 30720
#define KSL 8              // KNN candidate slices
#define NSL (NU_/KSL)      // 256 candidates per slice
#define BM2 128            // GEMM M tile
#define GT_ 512            // GEMM threads
#define LDA2 40
#define LDB2 264
#define GA_HI(s) ((s)*10240)
#define GA_LO(s) (20480 + (s)*10240)
#define GB_HI(s) (40960 + (s)*16896)
#define GB_LO(s) (74752 + (s)*16896)
#define SMEM_G 108544

// ---------------- device scratch ----------------
__device__ int  g_up_idx[B_*NU_];
__device__ int  g_down_idx[B_*ND_];
__device__ int  g_dst[B_*ND_*M_];
__device__ unsigned char g_isup[B_*N_];
__device__ int  g_deg[B_*N_];
__device__ int  g_off[B_*N_];
__device__ int  g_cur[B_*N_];
__device__ int  g_src[B_*ND_*M_];
__device__ float g_feat[(size_t)B_*ND_*H_];
__device__ __nv_bfloat16 g_Whi[KP_*H_];
__device__ __nv_bfloat16 g_Wlo[KP_*H_];
__device__ float g_pd[(size_t)B_*ND_*KSL*M_];
__device__ int   g_pi[(size_t)B_*ND_*KSL*M_];

__device__ __forceinline__ unsigned enc_f(float f){
    unsigned u = __float_as_uint(f);
    return (u & 0x80000000u) ? ~u : (u | 0x80000000u);
}
__device__ __forceinline__ void cpa16(void* dst, const void* src){
    unsigned d = (unsigned)__cvta_generic_to_shared(dst);
    asm volatile("cp.async.cg.shared.global [%0], [%1], 16;" :: "r"(d), "l"(src));
}

__device__ __forceinline__ int block_scan_excl(int val, int* s_warp, int tid){
    const int lane = tid & 31, wid = tid >> 5;
    int inc = val;
#pragma unroll
    for (int o = 1; o < 32; o <<= 1){
        int v = __shfl_up_sync(0xFFFFFFFFu, inc, o);
        if (lane >= o) inc += v;
    }
    if (lane == 31) s_warp[wid] = inc;
    __syncthreads();
    if (wid == 0){
        int w = (lane < 32) ? s_warp[lane] : 0;
#pragma unroll
        for (int o = 1; o < 32; o <<= 1){
            int v = __shfl_up_sync(0xFFFFFFFFu, w, o);
            if (lane >= o) w += v;
        }
        s_warp[lane] = w;
    }
    __syncthreads();
    int base = (wid > 0) ? s_warp[wid - 1] : 0;
    return base + inc - val;
}

// ---------------- K0: W split into hi/lo bf16 ----------------
__global__ void k_wsplit(const float* __restrict__ W){
    const int idx = blockIdx.x * 256 + threadIdx.x;
    if (idx >= KP_ * H_) return;
    const int k = idx / H_, n = idx % H_;
    const float w = (k < KD_) ? W[k * H_ + n] : 0.0f;
    const __nv_bfloat16 hi = __float2bfloat16(w);
    const __nv_bfloat16 lo = __float2bfloat16(w - __bfloat162float(hi));
    g_Whi[idx] = hi;
    g_Wlo[idx] = lo;
}

// ---------------- K1: top-25% selection ----------------
__global__ void k_select(const float* __restrict__ scores,
                         float* __restrict__ d_out, long long out_size){
    __shared__ unsigned s_enc[N_];
    __shared__ int s_warp[32];
    __shared__ int s_hist[256];
    __shared__ int s_bcast[2];
    const int b = blockIdx.x, tid = threadIdx.x;

    for (int i = tid; i < N_; i += 1024) g_deg[b * N_ + i] = 0;

    const float* sc = scores + (long long)b * N_;
    for (int i = tid; i < N_; i += 1024) s_enc[i] = enc_f(sc[i]);
    __syncthreads();

    unsigned prefix = 0, known = 0;
    int k = NU_;
    for (int lvl = 3; lvl >= 0; --lvl){
        if (tid < 256) s_hist[tid] = 0;
        __syncthreads();
        const int sh = lvl * 8;
        for (int i = tid; i < N_; i += 1024){
            unsigned e = s_enc[i];
            if ((e & known) == prefix) atomicAdd(&s_hist[(e >> sh) & 255], 1);
        }
        __syncthreads();
        if (tid == 0){
            int kk = k, bin = 255;
            while (bin > 0 && kk > s_hist[bin]) { kk -= s_hist[bin]; --bin; }
            s_bcast[0] = bin; s_bcast[1] = kk;
        }
        __syncthreads();
        prefix |= ((unsigned)s_bcast[0]) << sh;
        known  |= 0xFFu << sh;
        k = s_bcast[1];
        __syncthreads();
    }
    const unsigned T = prefix;

    if (tid == 0) s_bcast[0] = 0;
    __syncthreads();
    {
        int loc = 0;
        for (int i = tid; i < N_; i += 1024) if (s_enc[i] > T) loc++;
        atomicAdd(&s_bcast[0], loc);
    }
    __syncthreads();
    const int need_eq = NU_ - s_bcast[0];
    __syncthreads();

    const int base = tid * 8;
    int eqc = 0;
#pragma unroll
    for (int e = 0; e < 8; ++e) eqc += (s_enc[base + e] == T);
    int eqbase = block_scan_excl(eqc, s_warp, tid);
    __syncthreads();

    unsigned mbits = 0; int upc = 0;
    {
        int ec = eqbase;
#pragma unroll
        for (int e = 0; e < 8; ++e){
            unsigned v = s_enc[base + e];
            bool msk;
            if (v > T) msk = true;
            else if (v == T) { msk = (ec < need_eq); ec++; }
            else msk = false;
            if (msk) { mbits |= (1u << e); upc++; }
        }
    }
    int upbase = block_scan_excl(upc, s_warp, tid);

    const long long BNH = (long long)B_ * N_ * H_;
    const bool wf = (out_size == BNH + (long long)B_ * N_);
    const bool wb = (out_size == BNH + ((long long)B_ * N_) / 4);
    int up = upbase;
#pragma unroll
    for (int e = 0; e < 8; ++e){
        const int i = base + e;
        const bool msk = (mbits >> e) & 1;
        if (msk) { g_up_idx[b * NU_ + up] = i; up++; }
        else       g_down_idx[b * ND_ + (i - up)] = i;
        g_isup[b * N_ + i] = msk ? 1 : 0;
        if (wf)      d_out[BNH + (long long)b * N_ + i] = msk ? 1.0f : 0.0f;
        else if (wb) ((unsigned char*)d_out)[BNH * 4 + (long long)b * N_ + i] = msk ? 1 : 0;
    }
}

// -------- K2a: KNN phase 1 — scalar + batch-4 min guard, 2 pts/thread ------
struct Top5 { float d0,d1,d2,d3,d4; int i0,i1,i2,i3,i4; };
__device__ __forceinline__ void top5_init(Top5& t){
    const float INF = __int_as_float(0x7f800000);
    t.d0=t.d1=t.d2=t.d3=t.d4=INF; t.i0=t.i1=t.i2=t.i3=t.i4=0;
}
__device__ __forceinline__ void top5_ins(Top5& t, float d, int j){
    if (d < t.d4){
        if (d < t.d3){ t.d4=t.d3; t.i4=t.i3;
            if (d < t.d2){ t.d3=t.d2; t.i3=t.i2;
                if (d < t.d1){ t.d2=t.d1; t.i2=t.i1;
                    if (d < t.d0){ t.d1=t.d0; t.i1=t.i0; t.d0=d; t.i0=j; }
                    else        { t.d1=d;  t.i1=j; }
                } else { t.d2=d; t.i2=j; }
            } else { t.d3=d; t.i3=j; }
        } else { t.d4=d; t.i4=j; }
    }
}

__global__ void k_knn_part(const float* __restrict__ s_l){
    __shared__ float4 su[NSL];   // xyz + global idx bits in .w
    const int b  = blockIdx.y;
    const int sl = blockIdx.z;
    const int tid = threadIdx.x;
    for (int j = tid; j < NSL; j += 256){
        int u = g_up_idx[b * NU_ + sl * NSL + j];
        long long p = ((long long)b * N_ + u) * 3;
        su[j] = make_float4(s_l[p], s_l[p+1], s_l[p+2], __int_as_float(b * N_ + u));
    }
    __syncthreads();

    const int dlA = blockIdx.x * 512 + tid;   // grid.x = ND/512
    const int dlB = dlA + 256;
    const int dnA = g_down_idx[b * ND_ + dlA];
    const int dnB = g_down_idx[b * ND_ + dlB];
    long long pA = ((long long)b * N_ + dnA) * 3;
    long long pB = ((long long)b * N_ + dnB) * 3;
    const float xA = s_l[pA], yA = s_l[pA+1], zA = s_l[pA+2];
    const float xB = s_l[pB], yB = s_l[pB+1], zB = s_l[pB+2];

    Top5 tA, tB; top5_init(tA); top5_init(tB);
#pragma unroll 1
    for (int j = 0; j < NSL; j += 4){
        const float4 u0 = su[j],   u1 = su[j+1];
        const float4 u2 = su[j+2], u3 = su[j+3];

        float ax0 = xA-u0.x, ay0 = yA-u0.y, az0 = zA-u0.z;
        float ax1 = xA-u1.x, ay1 = yA-u1.y, az1 = zA-u1.z;
        float ax2 = xA-u2.x, ay2 = yA-u2.y, az2 = zA-u2.z;
        float ax3 = xA-u3.x, ay3 = yA-u3.y, az3 = zA-u3.z;
        float a0 = ax0*ax0 + ay0*ay0 + az0*az0;
        float a1 = ax1*ax1 + ay1*ay1 + az1*az1;
        float a2 = ax2*ax2 + ay2*ay2 + az2*az2;
        float a3 = ax3*ax3 + ay3*ay3 + az3*az3;

        float bx0 = xB-u0.x, by0 = yB-u0.y, bz0 = zB-u0.z;
        float bx1 = xB-u1.x, by1 = yB-u1.y, bz1 = zB-u1.z;
        float bx2 = xB-u2.x, by2 = yB-u2.y, bz2 = zB-u2.z;
        float bx3 = xB-u3.x, by3 = yB-u3.y, bz3 = zB-u3.z;
        float b0 = bx0*bx0 + by0*by0 + bz0*bz0;
        float b1 = bx1*bx1 + by1*by1 + bz1*bz1;
        float b2 = bx2*bx2 + by2*by2 + bz2*bz2;
        float b3 = bx3*bx3 + by3*by3 + bz3*bz3;

        const float mA = fminf(fminf(a0, a1), fminf(a2, a3));
        const float mB = fminf(fminf(b0, b1), fminf(b2, b3));
        // guard: if min of batch can't beat current 5th, skip all inserts.
        // Else sequential ascending-j strict-'<' inserts == lax.top_k exactly.
        if (mA < tA.d4){
            top5_ins(tA, a0, j);   top5_ins(tA, a1, j+1);
            top5_ins(tA, a2, j+2); top5_ins(tA, a3, j+3);
        }
        if (mB < tB.d4){
            top5_ins(tB, b0, j);   top5_ins(tB, b1, j+1);
            top5_ins(tB, b2, j+2); top5_ins(tB, b3, j+3);
        }
    }

    {
        const size_t base = (((size_t)b * ND_ + dlA) * KSL + sl) * M_;
        g_pd[base+0]=tA.d0; g_pd[base+1]=tA.d1; g_pd[base+2]=tA.d2;
        g_pd[base+3]=tA.d3; g_pd[base+4]=tA.d4;
        g_pi[base+0]=__float_as_int(su[tA.i0].w);
        g_pi[base+1]=__float_as_int(su[tA.i1].w);
        g_pi[base+2]=__float_as_int(su[tA.i2].w);
        g_pi[base+3]=__float_as_int(su[tA.i3].w);
        g_pi[base+4]=__float_as_int(su[tA.i4].w);
    }
    {
        const size_t base = (((size_t)b * ND_ + dlB) * KSL + sl) * M_;
        g_pd[base+0]=tB.d0; g_pd[base+1]=tB.d1; g_pd[base+2]=tB.d2;
        g_pd[base+3]=tB.d3; g_pd[base+4]=tB.d4;
        g_pi[base+0]=__float_as_int(su[tB.i0].w);
        g_pi[base+1]=__float_as_int(su[tB.i1].w);
        g_pi[base+2]=__float_as_int(su[tB.i2].w);
        g_pi[base+3]=__float_as_int(su[tB.i3].w);
        g_pi[base+4]=__float_as_int(su[tB.i4].w);
    }
}

// -------- K2b: KNN phase 2 — 8-way merge of sorted 5-lists + degrees --------
__global__ void k_knn_merge(){
    const int pt = blockIdx.x * 256 + threadIdx.x;
    if (pt >= B_ * ND_) return;
    const size_t b0 = (size_t)pt * KSL * M_;
    float ld[KSL][5]; int li[KSL][5];
#pragma unroll
    for (int s = 0; s < KSL; ++s)
#pragma unroll
        for (int q = 0; q < 5; ++q){
            ld[s][q] = g_pd[b0 + s*5 + q];
            li[s][q] = g_pi[b0 + s*5 + q];
        }
    int hp[KSL];
#pragma unroll
    for (int s = 0; s < KSL; ++s) hp[s] = 0;
    int* dst = g_dst + (size_t)pt * M_;
    const float INF = __int_as_float(0x7f800000);
#pragma unroll
    for (int k = 0; k < 5; ++k){
        int bs = 0; float bd = INF;
#pragma unroll
        for (int s = 0; s < KSL; ++s){
            float v = (hp[s] < 5) ? ld[s][hp[s]] : INF;
            if (v < bd){ bd = v; bs = s; }
        }
        int e = li[bs][hp[bs]];
        hp[bs]++;
        dst[k] = e;
        atomicAdd(&g_deg[e], 1);
    }
}

// -------- K3: per-graph exclusive scan --------
__global__ void k_scan(){
    __shared__ int s_warp[32];
    const int b = blockIdx.x, tid = threadIdx.x;
    const int base = b * N_ + tid * 8;
    int d[8]; int s = 0;
#pragma unroll
    for (int i = 0; i < 8; ++i){ d[i] = g_deg[base + i]; s += d[i]; }
    int run = block_scan_excl(s, s_warp, tid) + b * EPG;
#pragma unroll
    for (int i = 0; i < 8; ++i){
        g_off[base + i] = run;
        g_cur[base + i] = run;
        run += d[i];
    }
}

// ---------------- K4: CSR fill ----------------
__global__ void k_fill(){
    const int e = blockIdx.x * 256 + threadIdx.x;
    if (e >= B_ * ND_ * M_) return;
    const int dst = g_dst[e];
    const int pos = atomicAdd(&g_cur[dst], 1);
    g_src[pos] = e / M_;
}

// -------- K5: pipelined WMMA bf16 hi/lo GEMM, BM=128 x BN=256, 512 thr ------
__device__ __forceinline__ void loadA_regs(float* xs, const float* __restrict__ hh,
                                           const float* __restrict__ sl,
                                           const float* __restrict__ sc,
                                           int g, int c, int ah){
    if (c < 8){
        const float4* hp = (const float4*)(hh + (size_t)g * H_ + c * 32 + ah);
        float4 f0 = hp[0], f1 = hp[1];
        xs[0]=f0.x; xs[1]=f0.y; xs[2]=f0.z; xs[3]=f0.w;
        xs[4]=f1.x; xs[5]=f1.y; xs[6]=f1.z; xs[7]=f1.w;
    } else {
#pragma unroll
        for (int q = 0; q < 8; ++q) xs[q] = 0.0f;
        if (ah == 0){
            xs[0] = sl[(size_t)g * 3];
            xs[1] = sl[(size_t)g * 3 + 1];
            xs[2] = sl[(size_t)g * 3 + 2];
            xs[3] = sc[g];
        }
    }
}

__global__ void __launch_bounds__(GT_, 1)
k_gemm_tc(const float* __restrict__ hh, const float* __restrict__ sl,
          const float* __restrict__ sc){
    extern __shared__ char sm[];
    __shared__ int s_g[BM2];

    const int b   = blockIdx.y;
    const int m0  = blockIdx.x * BM2;
    const int tid = threadIdx.x;
    const int w   = tid >> 5;
    const int wm  = w >> 2;
    const int wn  = w & 3;

    if (tid < BM2) s_g[tid] = b * N_ + g_down_idx[b * ND_ + m0 + tid];
    __syncthreads();

    const int ar = tid >> 2;
    const int ah = (tid & 3) * 8;
    const int g  = s_g[ar];

    wmma::fragment<wmma::accumulator, 16, 16, 16, float> acc[2][4];
#pragma unroll
    for (int i = 0; i < 2; ++i)
#pragma unroll
        for (int j = 0; j < 4; ++j) wmma::fill_fragment(acc[i][j], 0.0f);

    auto copyB = [&](int c, int s){
        const int k0 = c * 32;
        __nv_bfloat16* Bh = (__nv_bfloat16*)(sm + GB_HI(s));
        __nv_bfloat16* Bl = (__nv_bfloat16*)(sm + GB_LO(s));
#pragma unroll
        for (int q = 0; q < 2; ++q){
            const int i = tid + q * GT_;
            const int row = i >> 5;
            const int col = (i & 31) * 8;
            cpa16(Bh + row * LDB2 + col, g_Whi + (size_t)(k0 + row) * H_ + col);
            cpa16(Bl + row * LDB2 + col, g_Wlo + (size_t)(k0 + row) * H_ + col);
        }
        asm volatile("cp.async.commit_group;");
    };
    auto storeA = [&](const float* xs, int s){
        unsigned hw[4], lw[4];
#pragma unroll
        for (int q = 0; q < 4; ++q){
            __nv_bfloat16 h0 = __float2bfloat16(xs[2*q]);
            __nv_bfloat16 h1 = __float2bfloat16(xs[2*q+1]);
            __nv_bfloat16 l0 = __float2bfloat16(xs[2*q]   - __bfloat162float(h0));
            __nv_bfloat16 l1 = __float2bfloat16(xs[2*q+1] - __bfloat162float(h1));
            __nv_bfloat162 hp2 = __nv_bfloat162(h0, h1);
            __nv_bfloat162 lp2 = __nv_bfloat162(l0, l1);
            hw[q] = *(unsigned*)&hp2;
            lw[q] = *(unsigned*)&lp2;
        }
        *(uint4*)((__nv_bfloat16*)(sm + GA_HI(s)) + ar * LDA2 + ah) =
            make_uint4(hw[0], hw[1], hw[2], hw[3]);
        *(uint4*)((__nv_bfloat16*)(sm + GA_LO(s)) + ar * LDA2 + ah) =
            make_uint4(lw[0], lw[1], lw[2], lw[3]);
    };

    float xs[8], xs2[8];
    loadA_regs(xs, hh, sl, sc, g, 0, ah);
    copyB(0, 0);

    for (int c = 0; c < 9; ++c){
        const int s = c & 1;
        if (c < 8){
            loadA_regs(xs2, hh, sl, sc, g, c + 1, ah);
            copyB(c + 1, s ^ 1);
        }
        storeA(xs, s);
        if (c < 8) asm volatile("cp.async.wait_group 1;");
        else       asm volatile("cp.async.wait_group 0;");
        __syncthreads();

        const __nv_bfloat16* Ah = (const __nv_bfloat16*)(sm + GA_HI(s));
        const __nv_bfloat16* Al = (const __nv_bfloat16*)(sm + GA_LO(s));
        const __nv_bfloat16* Bh = (const __nv_bfloat16*)(sm + GB_HI(s));
        const __nv_bfloat16* Bl = (const __nv_bfloat16*)(sm + GB_LO(s));
        // chunk 8 holds only k=256..259 (first k16 step); kt=1 is all zeros
        const int ktmax = (c == 8) ? 1 : 2;
#pragma unroll
        for (int kt = 0; kt < 2; ++kt){
            if (kt >= ktmax) break;
            const int ks = kt * 16;
            wmma::fragment<wmma::matrix_a, 16, 16, 16, __nv_bfloat16, wmma::row_major> fa_hi[2], fa_lo[2];
#pragma unroll
            for (int i = 0; i < 2; ++i){
                wmma::load_matrix_sync(fa_hi[i], Ah + (wm*32 + i*16) * LDA2 + ks, LDA2);
                wmma::load_matrix_sync(fa_lo[i], Al + (wm*32 + i*16) * LDA2 + ks, LDA2);
            }
#pragma unroll
            for (int j = 0; j < 4; ++j){
                wmma::fragment<wmma::matrix_b, 16, 16, 16, __nv_bfloat16, wmma::row_major> fb_hi, fb_lo;
                wmma::load_matrix_sync(fb_hi, Bh + ks * LDB2 + wn*64 + j*16, LDB2);
                wmma::load_matrix_sync(fb_lo, Bl + ks * LDB2 + wn*64 + j*16, LDB2);
#pragma unroll
                for (int i = 0; i < 2; ++i){
                    wmma::mma_sync(acc[i][j], fa_hi[i], fb_hi, acc[i][j]);
                    wmma::mma_sync(acc[i][j], fa_hi[i], fb_lo, acc[i][j]);
                    wmma::mma_sync(acc[i][j], fa_lo[i], fb_hi, acc[i][j]);
                }
            }
        }
        __syncthreads();
#pragma unroll
        for (int q = 0; q < 8; ++q) xs[q] = xs2[q];
    }

#pragma unroll
    for (int i = 0; i < 2; ++i){
        const int row = m0 + wm * 32 + i * 16;
#pragma unroll
        for (int j = 0; j < 4; ++j){
            const int col = wn * 64 + j * 16;
            wmma::store_matrix_sync(
                g_feat + ((size_t)b * ND_ + row) * H_ + col,
                acc[i][j], H_, wmma::mem_row_major);
        }
    }
}

// ---------------- K6: gather-max (+bias) into output ----------------
__global__ void k_gather(float* __restrict__ out, const float* __restrict__ bias){
    const int wid = threadIdx.x >> 5, lane = threadIdx.x & 31;
    const int row = blockIdx.x * 8 + wid;
    float* op = out + (size_t)row * H_;
    const int c0 = lane * 4;
    const float4 z = make_float4(0.f, 0.f, 0.f, 0.f);
    const int deg = g_deg[row];
    if (!g_isup[row] || deg == 0){
        *(float4*)(op + c0) = z;
        *(float4*)(op + c0 + 128) = z;
        return;
    }
    const int off = g_off[row];
    const float NI = __int_as_float(0xff800000);
    float4 a = make_float4(NI, NI, NI, NI), bq = a;
    for (int e = 0; e < deg; ++e){
        const float* fp = g_feat + (size_t)g_src[off + e] * H_;
        float4 u = *(const float4*)(fp + c0);
        float4 v = *(const float4*)(fp + c0 + 128);
        a.x = fmaxf(a.x, u.x); a.y = fmaxf(a.y, u.y);
        a.z = fmaxf(a.z, u.z); a.w = fmaxf(a.w, u.w);
        bq.x = fmaxf(bq.x, v.x); bq.y = fmaxf(bq.y, v.y);
        bq.z = fmaxf(bq.z, v.z); bq.w = fmaxf(bq.w, v.w);
    }
    const float4 ba = *(const float4*)(bias + c0);
    const float4 bb = *(const float4*)(bias + c0 + 128);
    a.x += ba.x; a.y += ba.y; a.z += ba.z; a.w += ba.w;
    bq.x += bb.x; bq.y += bb.y; bq.z += bb.z; bq.w += bb.w;
    *(float4*)(op + c0) = a;
    *(float4*)(op + c0 + 128) = bq;
}

// ------------------------------- launch ------------------------------------
extern "C" void kernel_launch(void* const* d_in, const int* in_sizes, int n_in,
                              void* d_out, int out_size){
    const float* hh = (const float*)d_in[0];
    const float* sl = (const float*)d_in[1];
    const float* sc = (const float*)d_in[2];
    const float* W  = (const float*)d_in[3];
    const float* bb = (const float*)d_in[4];
    (void)in_sizes; (void)n_in;

    cudaFuncSetAttribute(k_gemm_tc, cudaFuncAttributeMaxDynamicSharedMemorySize, SMEM_G);

    k_wsplit<<<(KP_*H_ + 255)/256, 256>>>(W);                       // 0
    k_select<<<B_, 1024>>>(sc, (float*)d_out, (long long)out_size); // 1
    dim3 gg(ND_ / BM2, B_);
    k_gemm_tc<<<gg, GT_, SMEM_G>>>(hh, sl, sc);                     // 2
    dim3 gknn(ND_ / 512, B_, KSL);
    k_knn_part<<<gknn, 256>>>(sl);                                   // 3 (profiled)
    k_knn_merge<<<(B_*ND_ + 255)/256, 256>>>();                      // 4
    k_scan<<<B_, 1024>>>();                                          // 5
    k_fill<<<(B_*ND_*M_ + 255)/256, 256>>>();                        // 6
    k_gather<<<B_*N_/8, 256>>>((float*)d_out, bb);                   // 7
}

// round 14
// speedup vs baseline: 1.1281x; 1.0957x over previous
#include <cuda_runtime.h>
#include <cuda_bf16.h>
#include <mma.h>
#include <cstdint>

using namespace nvcuda;

#define B_  8
#define N_  8192
#define H_  256
#define KD_ 260            // H + 4
#define KP_ 288            // K padded to 9*32
#define NU_ 2048
#define ND_ 6144
#define M_  5
#define EPG (ND_*M_)       // edges per graph = 30720
#define KSL 4              // KNN candidate slices
#define NSL (NU_/KSL)      // 512 candidates per slice
#define BM2 128            // GEMM M tile
#define GT_ 512            // GEMM threads
#define LDA2 40
#define LDB2 264
#define GA_HI(s) ((s)*10240)
#define GA_LO(s) (20480 + (s)*10240)
#define GB_HI(s) (40960 + (s)*16896)
#define GB_LO(s) (74752 + (s)*16896)
#define SMEM_G 108544

// ---------------- device scratch ----------------
__device__ int  g_up_idx[B_*NU_];
__device__ int  g_down_idx[B_*ND_];
__device__ int  g_dst[B_*ND_*M_];
__device__ unsigned char g_isup[B_*N_];
__device__ int  g_deg[B_*N_];
__device__ int  g_off[B_*N_];
__device__ int  g_cur[B_*N_];
__device__ int  g_src[B_*ND_*M_];
__device__ float g_feat[(size_t)B_*ND_*H_];
__device__ __nv_bfloat16 g_Whi[KP_*H_];
__device__ __nv_bfloat16 g_Wlo[KP_*H_];
__device__ float g_pd[(size_t)B_*ND_*KSL*M_];
__device__ int   g_pi[(size_t)B_*ND_*KSL*M_];

__device__ __forceinline__ unsigned enc_f(float f){
    unsigned u = __float_as_uint(f);
    return (u & 0x80000000u) ? ~u : (u | 0x80000000u);
}
__device__ __forceinline__ void cpa16(void* dst, const void* src){
    unsigned d = (unsigned)__cvta_generic_to_shared(dst);
    asm volatile("cp.async.cg.shared.global [%0], [%1], 16;" :: "r"(d), "l"(src));
}

__device__ __forceinline__ int block_scan_excl(int val, int* s_warp, int tid){
    const int lane = tid & 31, wid = tid >> 5;
    int inc = val;
#pragma unroll
    for (int o = 1; o < 32; o <<= 1){
        int v = __shfl_up_sync(0xFFFFFFFFu, inc, o);
        if (lane >= o) inc += v;
    }
    if (lane == 31) s_warp[wid] = inc;
    __syncthreads();
    if (wid == 0){
        int w = (lane < 32) ? s_warp[lane] : 0;
#pragma unroll
        for (int o = 1; o < 32; o <<= 1){
            int v = __shfl_up_sync(0xFFFFFFFFu, w, o);
            if (lane >= o) w += v;
        }
        s_warp[lane] = w;
    }
    __syncthreads();
    int base = (wid > 0) ? s_warp[wid - 1] : 0;
    return base + inc - val;
}

// ---------------- K0: W split into hi/lo bf16 ----------------
__global__ void k_wsplit(const float* __restrict__ W){
    const int idx = blockIdx.x * 256 + threadIdx.x;
    if (idx >= KP_ * H_) return;
    const int k = idx / H_, n = idx % H_;
    const float w = (k < KD_) ? W[k * H_ + n] : 0.0f;
    const __nv_bfloat16 hi = __float2bfloat16(w);
    const __nv_bfloat16 lo = __float2bfloat16(w - __bfloat162float(hi));
    g_Whi[idx] = hi;
    g_Wlo[idx] = lo;
}

// ---------------- K1: top-25% selection ----------------
__global__ void k_select(const float* __restrict__ scores,
                         float* __restrict__ d_out, long long out_size){
    __shared__ unsigned s_enc[N_];
    __shared__ int s_warp[32];
    __shared__ int s_hist[256];
    __shared__ int s_bcast[2];
    const int b = blockIdx.x, tid = threadIdx.x;

    for (int i = tid; i < N_; i += 1024) g_deg[b * N_ + i] = 0;

    const float* sc = scores + (long long)b * N_;
    for (int i = tid; i < N_; i += 1024) s_enc[i] = enc_f(sc[i]);
    __syncthreads();

    unsigned prefix = 0, known = 0;
    int k = NU_;
    for (int lvl = 3; lvl >= 0; --lvl){
        if (tid < 256) s_hist[tid] = 0;
        __syncthreads();
        const int sh = lvl * 8;
        for (int i = tid; i < N_; i += 1024){
            unsigned e = s_enc[i];
            if ((e & known) == prefix) atomicAdd(&s_hist[(e >> sh) & 255], 1);
        }
        __syncthreads();
        if (tid == 0){
            int kk = k, bin = 255;
            while (bin > 0 && kk > s_hist[bin]) { kk -= s_hist[bin]; --bin; }
            s_bcast[0] = bin; s_bcast[1] = kk;
        }
        __syncthreads();
        prefix |= ((unsigned)s_bcast[0]) << sh;
        known  |= 0xFFu << sh;
        k = s_bcast[1];
        __syncthreads();
    }
    const unsigned T = prefix;

    if (tid == 0) s_bcast[0] = 0;
    __syncthreads();
    {
        int loc = 0;
        for (int i = tid; i < N_; i += 1024) if (s_enc[i] > T) loc++;
        atomicAdd(&s_bcast[0], loc);
    }
    __syncthreads();
    const int need_eq = NU_ - s_bcast[0];
    __syncthreads();

    const int base = tid * 8;
    int eqc = 0;
#pragma unroll
    for (int e = 0; e < 8; ++e) eqc += (s_enc[base + e] == T);
    int eqbase = block_scan_excl(eqc, s_warp, tid);
    __syncthreads();

    unsigned mbits = 0; int upc = 0;
    {
        int ec = eqbase;
#pragma unroll
        for (int e = 0; e < 8; ++e){
            unsigned v = s_enc[base + e];
            bool msk;
            if (v > T) msk = true;
            else if (v == T) { msk = (ec < need_eq); ec++; }
            else msk = false;
            if (msk) { mbits |= (1u << e); upc++; }
        }
    }
    int upbase = block_scan_excl(upc, s_warp, tid);

    const long long BNH = (long long)B_ * N_ * H_;
    const bool wf = (out_size == BNH + (long long)B_ * N_);
    const bool wb = (out_size == BNH + ((long long)B_ * N_) / 4);
    int up = upbase;
#pragma unroll
    for (int e = 0; e < 8; ++e){
        const int i = base + e;
        const bool msk = (mbits >> e) & 1;
        if (msk) { g_up_idx[b * NU_ + up] = i; up++; }
        else       g_down_idx[b * ND_ + (i - up)] = i;
        g_isup[b * N_ + i] = msk ? 1 : 0;
        if (wf)      d_out[BNH + (long long)b * N_ + i] = msk ? 1.0f : 0.0f;
        else if (wb) ((unsigned char*)d_out)[BNH * 4 + (long long)b * N_ + i] = msk ? 1 : 0;
    }
}

// -------- K2a: KNN phase 1 — 1 pt/thread, batch-8 min guard --------
struct Top5 { float d0,d1,d2,d3,d4; int i0,i1,i2,i3,i4; };
__device__ __forceinline__ void top5_init(Top5& t){
    const float INF = __int_as_float(0x7f800000);
    t.d0=t.d1=t.d2=t.d3=t.d4=INF; t.i0=t.i1=t.i2=t.i3=t.i4=0;
}
__device__ __forceinline__ void top5_ins(Top5& t, float d, int j){
    if (d < t.d4){
        if (d < t.d3){ t.d4=t.d3; t.i4=t.i3;
            if (d < t.d2){ t.d3=t.d2; t.i3=t.i2;
                if (d < t.d1){ t.d2=t.d1; t.i2=t.i1;
                    if (d < t.d0){ t.d1=t.d0; t.i1=t.i0; t.d0=d; t.i0=j; }
                    else        { t.d1=d;  t.i1=j; }
                } else { t.d2=d; t.i2=j; }
            } else { t.d3=d; t.i3=j; }
        } else { t.d4=d; t.i4=j; }
    }
}

__global__ void k_knn_part(const float* __restrict__ s_l){
    __shared__ float4 su[NSL];   // xyz + global idx bits in .w
    const int b  = blockIdx.y;
    const int sl = blockIdx.z;
    const int tid = threadIdx.x;
    for (int j = tid; j < NSL; j += 256){
        int u = g_up_idx[b * NU_ + sl * NSL + j];
        long long p = ((long long)b * N_ + u) * 3;
        su[j] = make_float4(s_l[p], s_l[p+1], s_l[p+2], __int_as_float(b * N_ + u));
    }
    __syncthreads();

    const int dl = blockIdx.x * 256 + tid;   // grid.x = ND/256
    const int dn = g_down_idx[b * ND_ + dl];
    long long p = ((long long)b * N_ + dn) * 3;
    const float x = s_l[p], y = s_l[p+1], z = s_l[p+2];

    Top5 t; top5_init(t);
#pragma unroll 1
    for (int j = 0; j < NSL; j += 8){
        float d[8];
#pragma unroll
        for (int q = 0; q < 8; ++q){
            const float4 u = su[j + q];
            float dx = x - u.x, dy = y - u.y, dz = z - u.z;
            d[q] = dx*dx + dy*dy + dz*dz;
        }
        float mn = fminf(fminf(fminf(d[0], d[1]), fminf(d[2], d[3])),
                         fminf(fminf(d[4], d[5]), fminf(d[6], d[7])));
        // guard: skip SEL-chain work unless some candidate can enter top-5.
        // On hit: sequential ascending-j strict-'<' inserts == lax.top_k.
        if (mn < t.d4){
#pragma unroll
            for (int q = 0; q < 8; ++q) top5_ins(t, d[q], j + q);
        }
    }

    const size_t base = (((size_t)b * ND_ + dl) * KSL + sl) * M_;
    g_pd[base+0]=t.d0; g_pd[base+1]=t.d1; g_pd[base+2]=t.d2;
    g_pd[base+3]=t.d3; g_pd[base+4]=t.d4;
    g_pi[base+0]=__float_as_int(su[t.i0].w);
    g_pi[base+1]=__float_as_int(su[t.i1].w);
    g_pi[base+2]=__float_as_int(su[t.i2].w);
    g_pi[base+3]=__float_as_int(su[t.i3].w);
    g_pi[base+4]=__float_as_int(su[t.i4].w);
}

// -------- K2b: KNN phase 2 — 4-way merge of sorted 5-lists + degrees --------
__global__ void k_knn_merge(){
    const int pt = blockIdx.x * 256 + threadIdx.x;
    if (pt >= B_ * ND_) return;
    const size_t b0 = (size_t)pt * KSL * M_;
    float ld[KSL][5]; int li[KSL][5];
#pragma unroll
    for (int s = 0; s < KSL; ++s)
#pragma unroll
        for (int q = 0; q < 5; ++q){
            ld[s][q] = g_pd[b0 + s*5 + q];
            li[s][q] = g_pi[b0 + s*5 + q];
        }
    int hp[KSL];
#pragma unroll
    for (int s = 0; s < KSL; ++s) hp[s] = 0;
    int* dst = g_dst + (size_t)pt * M_;
    const float INF = __int_as_float(0x7f800000);
#pragma unroll
    for (int k = 0; k < 5; ++k){
        int bs = 0; float bd = INF;
#pragma unroll
        for (int s = 0; s < KSL; ++s){
            float v = (hp[s] < 5) ? ld[s][hp[s]] : INF;
            if (v < bd){ bd = v; bs = s; }
        }
        int e = li[bs][hp[bs]];
        hp[bs]++;
        dst[k] = e;
        atomicAdd(&g_deg[e], 1);
    }
}

// -------- K3: per-graph exclusive scan --------
__global__ void k_scan(){
    __shared__ int s_warp[32];
    const int b = blockIdx.x, tid = threadIdx.x;
    const int base = b * N_ + tid * 8;
    int d[8]; int s = 0;
#pragma unroll
    for (int i = 0; i < 8; ++i){ d[i] = g_deg[base + i]; s += d[i]; }
    int run = block_scan_excl(s, s_warp, tid) + b * EPG;
#pragma unroll
    for (int i = 0; i < 8; ++i){
        g_off[base + i] = run;
        g_cur[base + i] = run;
        run += d[i];
    }
}

// ---------------- K4: CSR fill ----------------
__global__ void k_fill(){
    const int e = blockIdx.x * 256 + threadIdx.x;
    if (e >= B_ * ND_ * M_) return;
    const int dst = g_dst[e];
    const int pos = atomicAdd(&g_cur[dst], 1);
    g_src[pos] = e / M_;
}

// -------- K5: pipelined WMMA bf16 hi/lo GEMM, BM=128 x BN=256, 512 thr ------
__device__ __forceinline__ void loadA_regs(float* xs, const float* __restrict__ hh,
                                           const float* __restrict__ sl,
                                           const float* __restrict__ sc,
                                           int g, int c, int ah){
    if (c < 8){
        const float4* hp = (const float4*)(hh + (size_t)g * H_ + c * 32 + ah);
        float4 f0 = hp[0], f1 = hp[1];
        xs[0]=f0.x; xs[1]=f0.y; xs[2]=f0.z; xs[3]=f0.w;
        xs[4]=f1.x; xs[5]=f1.y; xs[6]=f1.z; xs[7]=f1.w;
    } else {
#pragma unroll
        for (int q = 0; q < 8; ++q) xs[q] = 0.0f;
        if (ah == 0){
            xs[0] = sl[(size_t)g * 3];
            xs[1] = sl[(size_t)g * 3 + 1];
            xs[2] = sl[(size_t)g * 3 + 2];
            xs[3] = sc[g];
        }
    }
}

__global__ void __launch_bounds__(GT_, 1)
k_gemm_tc(const float* __restrict__ hh, const float* __restrict__ sl,
          const float* __restrict__ sc){
    extern __shared__ char sm[];
    __shared__ int s_g[BM2];

    const int b   = blockIdx.y;
    const int m0  = blockIdx.x * BM2;
    const int tid = threadIdx.x;
    const int w   = tid >> 5;
    const int wm  = w >> 2;
    const int wn  = w & 3;

    if (tid < BM2) s_g[tid] = b * N_ + g_down_idx[b * ND_ + m0 + tid];
    __syncthreads();

    const int ar = tid >> 2;
    const int ah = (tid & 3) * 8;
    const int g  = s_g[ar];

    wmma::fragment<wmma::accumulator, 16, 16, 16, float> acc[2][4];
#pragma unroll
    for (int i = 0; i < 2; ++i)
#pragma unroll
        for (int j = 0; j < 4; ++j) wmma::fill_fragment(acc[i][j], 0.0f);

    auto copyB = [&](int c, int s){
        const int k0 = c * 32;
        __nv_bfloat16* Bh = (__nv_bfloat16*)(sm + GB_HI(s));
        __nv_bfloat16* Bl = (__nv_bfloat16*)(sm + GB_LO(s));
#pragma unroll
        for (int q = 0; q < 2; ++q){
            const int i = tid + q * GT_;
            const int row = i >> 5;
            const int col = (i & 31) * 8;
            cpa16(Bh + row * LDB2 + col, g_Whi + (size_t)(k0 + row) * H_ + col);
            cpa16(Bl + row * LDB2 + col, g_Wlo + (size_t)(k0 + row) * H_ + col);
        }
        asm volatile("cp.async.commit_group;");
    };
    auto storeA = [&](const float* xs, int s){
        unsigned hw[4], lw[4];
#pragma unroll
        for (int q = 0; q < 4; ++q){
            __nv_bfloat16 h0 = __float2bfloat16(xs[2*q]);
            __nv_bfloat16 h1 = __float2bfloat16(xs[2*q+1]);
            __nv_bfloat16 l0 = __float2bfloat16(xs[2*q]   - __bfloat162float(h0));
            __nv_bfloat16 l1 = __float2bfloat16(xs[2*q+1] - __bfloat162float(h1));
            __nv_bfloat162 hp2 = __nv_bfloat162(h0, h1);
            __nv_bfloat162 lp2 = __nv_bfloat162(l0, l1);
            hw[q] = *(unsigned*)&hp2;
            lw[q] = *(unsigned*)&lp2;
        }
        *(uint4*)((__nv_bfloat16*)(sm + GA_HI(s)) + ar * LDA2 + ah) =
            make_uint4(hw[0], hw[1], hw[2], hw[3]);
        *(uint4*)((__nv_bfloat16*)(sm + GA_LO(s)) + ar * LDA2 + ah) =
            make_uint4(lw[0], lw[1], lw[2], lw[3]);
    };

    float xs[8], xs2[8];
    loadA_regs(xs, hh, sl, sc, g, 0, ah);
    copyB(0, 0);

    for (int c = 0; c < 9; ++c){
        const int s = c & 1;
        if (c < 8){
            loadA_regs(xs2, hh, sl, sc, g, c + 1, ah);
            copyB(c + 1, s ^ 1);
        }
        storeA(xs, s);
        if (c < 8) asm volatile("cp.async.wait_group 1;");
        else       asm volatile("cp.async.wait_group 0;");
        __syncthreads();

        const __nv_bfloat16* Ah = (const __nv_bfloat16*)(sm + GA_HI(s));
        const __nv_bfloat16* Al = (const __nv_bfloat16*)(sm + GA_LO(s));
        const __nv_bfloat16* Bh = (const __nv_bfloat16*)(sm + GB_HI(s));
        const __nv_bfloat16* Bl = (const __nv_bfloat16*)(sm + GB_LO(s));
        // chunk 8 holds only k=256..259 (first k16 step); kt=1 is all zeros
        const int ktmax = (c == 8) ? 1 : 2;
#pragma unroll
        for (int kt = 0; kt < 2; ++kt){
            if (kt >= ktmax) break;
            const int ks = kt * 16;
            wmma::fragment<wmma::matrix_a, 16, 16, 16, __nv_bfloat16, wmma::row_major> fa_hi[2], fa_lo[2];
#pragma unroll
            for (int i = 0; i < 2; ++i){
                wmma::load_matrix_sync(fa_hi[i], Ah + (wm*32 + i*16) * LDA2 + ks, LDA2);
                wmma::load_matrix_sync(fa_lo[i], Al + (wm*32 + i*16) * LDA2 + ks, LDA2);
            }
#pragma unroll
            for (int j = 0; j < 4; ++j){
                wmma::fragment<wmma::matrix_b, 16, 16, 16, __nv_bfloat16, wmma::row_major> fb_hi, fb_lo;
                wmma::load_matrix_sync(fb_hi, Bh + ks * LDB2 + wn*64 + j*16, LDB2);
                wmma::load_matrix_sync(fb_lo, Bl + ks * LDB2 + wn*64 + j*16, LDB2);
#pragma unroll
                for (int i = 0; i < 2; ++i){
                    wmma::mma_sync(acc[i][j], fa_hi[i], fb_hi, acc[i][j]);
                    wmma::mma_sync(acc[i][j], fa_hi[i], fb_lo, acc[i][j]);
                    wmma::mma_sync(acc[i][j], fa_lo[i], fb_hi, acc[i][j]);
                }
            }
        }
        __syncthreads();
#pragma unroll
        for (int q = 0; q < 8; ++q) xs[q] = xs2[q];
    }

#pragma unroll
    for (int i = 0; i < 2; ++i){
        const int row = m0 + wm * 32 + i * 16;
#pragma unroll
        for (int j = 0; j < 4; ++j){
            const int col = wn * 64 + j * 16;
            wmma::store_matrix_sync(
                g_feat + ((size_t)b * ND_ + row) * H_ + col,
                acc[i][j], H_, wmma::mem_row_major);
        }
    }
}

// ---------------- K6: gather-max (+bias) into output ----------------
__global__ void k_gather(float* __restrict__ out, const float* __restrict__ bias){
    const int wid = threadIdx.x >> 5, lane = threadIdx.x & 31;
    const int row = blockIdx.x * 8 + wid;
    float* op = out + (size_t)row * H_;
    const int c0 = lane * 4;
    const float4 z = make_float4(0.f, 0.f, 0.f, 0.f);
    const int deg = g_deg[row];
    if (!g_isup[row] || deg == 0){
        *(float4*)(op + c0) = z;
        *(float4*)(op + c0 + 128) = z;
        return;
    }
    const int off = g_off[row];
    const float NI = __int_as_float(0xff800000);
    float4 a = make_float4(NI, NI, NI, NI), bq = a;
    for (int e = 0; e < deg; ++e){
        const float* fp = g_feat + (size_t)g_src[off + e] * H_;
        float4 u = *(const float4*)(fp + c0);
        float4 v = *(const float4*)(fp + c0 + 128);
        a.x = fmaxf(a.x, u.x); a.y = fmaxf(a.y, u.y);
        a.z = fmaxf(a.z, u.z); a.w = fmaxf(a.w, u.w);
        bq.x = fmaxf(bq.x, v.x); bq.y = fmaxf(bq.y, v.y);
        bq.z = fmaxf(bq.z, v.z); bq.w = fmaxf(bq.w, v.w);
    }
    const float4 ba = *(const float4*)(bias + c0);
    const float4 bb = *(const float4*)(bias + c0 + 128);
    a.x += ba.x; a.y += ba.y; a.z += ba.z; a.w += ba.w;
    bq.x += bb.x; bq.y += bb.y; bq.z += bb.z; bq.w += bb.w;
    *(float4*)(op + c0) = a;
    *(float4*)(op + c0 + 128) = bq;
}

// ------------------------------- launch ------------------------------------
extern "C" void kernel_launch(void* const* d_in, const int* in_sizes, int n_in,
                              void* d_out, int out_size){
    const float* hh = (const float*)d_in[0];
    const float* sl = (const float*)d_in[1];
    const float* sc = (const float*)d_in[2];
    const float* W  = (const float*)d_in[3];
    const float* bb = (const float*)d_in[4];
    (void)in_sizes; (void)n_in;

    cudaFuncSetAttribute(k_gemm_tc, cudaFuncAttributeMaxDynamicSharedMemorySize, SMEM_G);

    k_wsplit<<<(KP_*H_ + 255)/256, 256>>>(W);                       // 0
    k_select<<<B_, 1024>>>(sc, (float*)d_out, (long long)out_size); // 1
    dim3 gg(ND_ / BM2, B_);
    k_gemm_tc<<<gg, GT_, SMEM_G>>>(hh, sl, sc);                     // 2
    dim3 gknn(ND_ / 256, B_, KSL);
    k_knn_part<<<gknn, 256>>>(sl);                                   // 3 (profiled)
    k_knn_merge<<<(B_*ND_ + 255)/256, 256>>>();                      // 4
    k_scan<<<B_, 1024>>>();                                          // 5
    k_fill<<<(B_*ND_*M_ + 255)/256, 256>>>();                        // 6
    k_gather<<<B_*N_/8, 256>>>((float*)d_out, bb);                   // 7
}

// round 15
// speedup vs baseline: 1.1372x; 1.0081x over previous
#include <cuda_runtime.h>
#include <cuda_bf16.h>
#include <mma.h>
#include <cstdint>

using namespace nvcuda;

#define B_  8
#define N_  8192
#define H_  256
#define KD_ 260            // H + 4
#define KP_ 288            // K padded to 9*32
#define NU_ 2048
#define ND_ 6144
#define M_  5
#define EPG (ND_*M_)       // edges per graph = 30720
#define KSL 4              // KNN candidate slices
#define NSL (NU_/KSL)      // 512 candidates per slice
#define CHK 3              // point-chunks per knn CTA (24 chunks / 8 blocks)
#define BM2 64             // GEMM M tile (256-thread version for co-residency)
#define LDA2 40
#define LDB2 264
#define OFF_AHI(s) ((s)*5120)
#define OFF_ALO(s) (10240 + (s)*5120)
#define OFF_BHI(s) (20480 + (s)*16896)
#define OFF_BLO(s) (54272 + (s)*16896)
#define SMEM_G 88064

// ---------------- device scratch ----------------
__device__ int  g_up_idx[B_*NU_];
__device__ int  g_down_idx[B_*ND_];
__device__ int  g_dst[B_*ND_*M_];
__device__ unsigned char g_isup[B_*N_];
__device__ int  g_deg[B_*N_];
__device__ int  g_off[B_*N_];
__device__ int  g_cur[B_*N_];
__device__ int  g_src[B_*ND_*M_];
__device__ float g_feat[(size_t)B_*ND_*H_];
__device__ __nv_bfloat16 g_Whi[KP_*H_];
__device__ __nv_bfloat16 g_Wlo[KP_*H_];
__device__ float g_pd[(size_t)B_*ND_*KSL*M_];
__device__ int   g_pi[(size_t)B_*ND_*KSL*M_];

__device__ __forceinline__ unsigned enc_f(float f){
    unsigned u = __float_as_uint(f);
    return (u & 0x80000000u) ? ~u : (u | 0x80000000u);
}
__device__ __forceinline__ void cpa16(void* dst, const void* src){
    unsigned d = (unsigned)__cvta_generic_to_shared(dst);
    asm volatile("cp.async.cg.shared.global [%0], [%1], 16;" :: "r"(d), "l"(src));
}

__device__ __forceinline__ int block_scan_excl(int val, int* s_warp, int tid){
    const int lane = tid & 31, wid = tid >> 5;
    int inc = val;
#pragma unroll
    for (int o = 1; o < 32; o <<= 1){
        int v = __shfl_up_sync(0xFFFFFFFFu, inc, o);
        if (lane >= o) inc += v;
    }
    if (lane == 31) s_warp[wid] = inc;
    __syncthreads();
    if (wid == 0){
        int w = (lane < 32) ? s_warp[lane] : 0;
#pragma unroll
        for (int o = 1; o < 32; o <<= 1){
            int v = __shfl_up_sync(0xFFFFFFFFu, w, o);
            if (lane >= o) w += v;
        }
        s_warp[lane] = w;
    }
    __syncthreads();
    int base = (wid > 0) ? s_warp[wid - 1] : 0;
    return base + inc - val;
}

// ---------------- K0: W split into hi/lo bf16 ----------------
__global__ void k_wsplit(const float* __restrict__ W){
    const int idx = blockIdx.x * 256 + threadIdx.x;
    if (idx >= KP_ * H_) return;
    const int k = idx / H_, n = idx % H_;
    const float w = (k < KD_) ? W[k * H_ + n] : 0.0f;
    const __nv_bfloat16 hi = __float2bfloat16(w);
    const __nv_bfloat16 lo = __float2bfloat16(w - __bfloat162float(hi));
    g_Whi[idx] = hi;
    g_Wlo[idx] = lo;
}

// ---------------- K1: top-25% selection ----------------
__global__ void k_select(const float* __restrict__ scores,
                         float* __restrict__ d_out, long long out_size){
    __shared__ unsigned s_enc[N_];
    __shared__ int s_warp[32];
    __shared__ int s_hist[256];
    __shared__ int s_bcast[2];
    const int b = blockIdx.x, tid = threadIdx.x;

    for (int i = tid; i < N_; i += 1024) g_deg[b * N_ + i] = 0;

    const float* sc = scores + (long long)b * N_;
    for (int i = tid; i < N_; i += 1024) s_enc[i] = enc_f(sc[i]);
    __syncthreads();

    unsigned prefix = 0, known = 0;
    int k = NU_;
    for (int lvl = 3; lvl >= 0; --lvl){
        if (tid < 256) s_hist[tid] = 0;
        __syncthreads();
        const int sh = lvl * 8;
        for (int i = tid; i < N_; i += 1024){
            unsigned e = s_enc[i];
            if ((e & known) == prefix) atomicAdd(&s_hist[(e >> sh) & 255], 1);
        }
        __syncthreads();
        if (tid == 0){
            int kk = k, bin = 255;
            while (bin > 0 && kk > s_hist[bin]) { kk -= s_hist[bin]; --bin; }
            s_bcast[0] = bin; s_bcast[1] = kk;
        }
        __syncthreads();
        prefix |= ((unsigned)s_bcast[0]) << sh;
        known  |= 0xFFu << sh;
        k = s_bcast[1];
        __syncthreads();
    }
    const unsigned T = prefix;

    if (tid == 0) s_bcast[0] = 0;
    __syncthreads();
    {
        int loc = 0;
        for (int i = tid; i < N_; i += 1024) if (s_enc[i] > T) loc++;
        atomicAdd(&s_bcast[0], loc);
    }
    __syncthreads();
    const int need_eq = NU_ - s_bcast[0];
    __syncthreads();

    const int base = tid * 8;
    int eqc = 0;
#pragma unroll
    for (int e = 0; e < 8; ++e) eqc += (s_enc[base + e] == T);
    int eqbase = block_scan_excl(eqc, s_warp, tid);
    __syncthreads();

    unsigned mbits = 0; int upc = 0;
    {
        int ec = eqbase;
#pragma unroll
        for (int e = 0; e < 8; ++e){
            unsigned v = s_enc[base + e];
            bool msk;
            if (v > T) msk = true;
            else if (v == T) { msk = (ec < need_eq); ec++; }
            else msk = false;
            if (msk) { mbits |= (1u << e); upc++; }
        }
    }
    int upbase = block_scan_excl(upc, s_warp, tid);

    const long long BNH = (long long)B_ * N_ * H_;
    const bool wf = (out_size == BNH + (long long)B_ * N_);
    const bool wb = (out_size == BNH + ((long long)B_ * N_) / 4);
    int up = upbase;
#pragma unroll
    for (int e = 0; e < 8; ++e){
        const int i = base + e;
        const bool msk = (mbits >> e) & 1;
        if (msk) { g_up_idx[b * NU_ + up] = i; up++; }
        else       g_down_idx[b * ND_ + (i - up)] = i;
        g_isup[b * N_ + i] = msk ? 1 : 0;
        if (wf)      d_out[BNH + (long long)b * N_ + i] = msk ? 1.0f : 0.0f;
        else if (wb) ((unsigned char*)d_out)[BNH * 4 + (long long)b * N_ + i] = msk ? 1 : 0;
    }
}

// -------- K2a: KNN phase 1 — 256 CTAs, 3 chunks/CTA, PDL trigger --------
struct Top5 { float d0,d1,d2,d3,d4; int i0,i1,i2,i3,i4; };
__device__ __forceinline__ void top5_init(Top5& t){
    const float INF = __int_as_float(0x7f800000);
    t.d0=t.d1=t.d2=t.d3=t.d4=INF; t.i0=t.i1=t.i2=t.i3=t.i4=0;
}
__device__ __forceinline__ void top5_ins(Top5& t, float d, int j){
    if (d < t.d4){
        if (d < t.d3){ t.d4=t.d3; t.i4=t.i3;
            if (d < t.d2){ t.d3=t.d2; t.i3=t.i2;
                if (d < t.d1){ t.d2=t.d1; t.i2=t.i1;
                    if (d < t.d0){ t.d1=t.d0; t.i1=t.i0; t.d0=d; t.i0=j; }
                    else        { t.d1=d;  t.i1=j; }
                } else { t.d2=d; t.i2=j; }
            } else { t.d3=d; t.i3=j; }
        } else { t.d4=d; t.i4=j; }
    }
}

__global__ void __launch_bounds__(256)
k_knn_part(const float* __restrict__ s_l){
    // PDL: allow the dependent (gemm) to launch; all 256 CTAs are resident
    // in wave 1 so this fires ~immediately.
    asm volatile("griddepcontrol.launch_dependents;" ::: "memory");

    __shared__ float4 su[NSL];   // xyz + global idx bits in .w
    const int b  = blockIdx.y;
    const int sl = blockIdx.z;
    const int tid = threadIdx.x;
    for (int j = tid; j < NSL; j += 256){
        int u = g_up_idx[b * NU_ + sl * NSL + j];
        long long p = ((long long)b * N_ + u) * 3;
        su[j] = make_float4(s_l[p], s_l[p+1], s_l[p+2], __int_as_float(b * N_ + u));
    }
    __syncthreads();

    for (int c = 0; c < CHK; ++c){
        const int dl = (blockIdx.x * CHK + c) * 256 + tid;
        const int dn = g_down_idx[b * ND_ + dl];
        long long p = ((long long)b * N_ + dn) * 3;
        const float x = s_l[p], y = s_l[p+1], z = s_l[p+2];

        Top5 t; top5_init(t);
        for (int j0 = 0; j0 < NSL; j0 += 4){
            const float4 u0 = su[j0], u1 = su[j0+1], u2 = su[j0+2], u3 = su[j0+3];
            float dx0 = x-u0.x, dy0 = y-u0.y, dz0 = z-u0.z;
            float dx1 = x-u1.x, dy1 = y-u1.y, dz1 = z-u1.z;
            float dx2 = x-u2.x, dy2 = y-u2.y, dz2 = z-u2.z;
            float dx3 = x-u3.x, dy3 = y-u3.y, dz3 = z-u3.z;
            float dA = dx0*dx0 + dy0*dy0 + dz0*dz0;
            float dB = dx1*dx1 + dy1*dy1 + dz1*dz1;
            float dC = dx2*dx2 + dy2*dy2 + dz2*dz2;
            float dD = dx3*dx3 + dy3*dy3 + dz3*dz3;
            top5_ins(t, dA, j0);
            top5_ins(t, dB, j0+1);
            top5_ins(t, dC, j0+2);
            top5_ins(t, dD, j0+3);
        }
        const size_t base = (((size_t)b * ND_ + dl) * KSL + sl) * M_;
        g_pd[base+0]=t.d0; g_pd[base+1]=t.d1; g_pd[base+2]=t.d2;
        g_pd[base+3]=t.d3; g_pd[base+4]=t.d4;
        g_pi[base+0]=__float_as_int(su[t.i0].w);
        g_pi[base+1]=__float_as_int(su[t.i1].w);
        g_pi[base+2]=__float_as_int(su[t.i2].w);
        g_pi[base+3]=__float_as_int(su[t.i3].w);
        g_pi[base+4]=__float_as_int(su[t.i4].w);
    }
}

// -------- K2b: KNN phase 2 — 4-way merge of sorted 5-lists + degrees --------
__global__ void k_knn_merge(){
    const int pt = blockIdx.x * 256 + threadIdx.x;
    if (pt >= B_ * ND_) return;
    const size_t b0 = (size_t)pt * KSL * M_;
    float ld[KSL][5]; int li[KSL][5];
#pragma unroll
    for (int s = 0; s < KSL; ++s)
#pragma unroll
        for (int q = 0; q < 5; ++q){
            ld[s][q] = g_pd[b0 + s*5 + q];
            li[s][q] = g_pi[b0 + s*5 + q];
        }
    int hp[KSL];
#pragma unroll
    for (int s = 0; s < KSL; ++s) hp[s] = 0;
    int* dst = g_dst + (size_t)pt * M_;
    const float INF = __int_as_float(0x7f800000);
#pragma unroll
    for (int k = 0; k < 5; ++k){
        int bs = 0; float bd = INF;
#pragma unroll
        for (int s = 0; s < KSL; ++s){
            float v = (hp[s] < 5) ? ld[s][hp[s]] : INF;
            if (v < bd){ bd = v; bs = s; }
        }
        int e = li[bs][hp[bs]];
        hp[bs]++;
        dst[k] = e;
        atomicAdd(&g_deg[e], 1);
    }
}

// -------- K3: per-graph exclusive scan --------
__global__ void k_scan(){
    __shared__ int s_warp[32];
    const int b = blockIdx.x, tid = threadIdx.x;
    const int base = b * N_ + tid * 8;
    int d[8]; int s = 0;
#pragma unroll
    for (int i = 0; i < 8; ++i){ d[i] = g_deg[base + i]; s += d[i]; }
    int run = block_scan_excl(s, s_warp, tid) + b * EPG;
#pragma unroll
    for (int i = 0; i < 8; ++i){
        g_off[base + i] = run;
        g_cur[base + i] = run;
        run += d[i];
    }
}

// ---------------- K4: CSR fill ----------------
__global__ void k_fill(){
    const int e = blockIdx.x * 256 + threadIdx.x;
    if (e >= B_ * ND_ * M_) return;
    const int dst = g_dst[e];
    const int pos = atomicAdd(&g_cur[dst], 1);
    g_src[pos] = e / M_;
}

// -------- K5: pipelined WMMA bf16 hi/lo GEMM, BM=64 x BN=256, 256 thr ------
__device__ __forceinline__ void loadA_regs(float* xs, const float* __restrict__ hh,
                                           const float* __restrict__ sl,
                                           const float* __restrict__ sc,
                                           int g, int c, int ah){
    if (c < 8){
        const float4* hp = (const float4*)(hh + (size_t)g * H_ + c * 32 + ah);
        float4 f0 = hp[0], f1 = hp[1];
        xs[0]=f0.x; xs[1]=f0.y; xs[2]=f0.z; xs[3]=f0.w;
        xs[4]=f1.x; xs[5]=f1.y; xs[6]=f1.z; xs[7]=f1.w;
    } else {
#pragma unroll
        for (int q = 0; q < 8; ++q) xs[q] = 0.0f;
        if (ah == 0){
            xs[0] = sl[(size_t)g * 3];
            xs[1] = sl[(size_t)g * 3 + 1];
            xs[2] = sl[(size_t)g * 3 + 2];
            xs[3] = sc[g];
        }
    }
}

__global__ void __launch_bounds__(256)
k_gemm_tc(const float* __restrict__ hh, const float* __restrict__ sl,
          const float* __restrict__ sc){
    extern __shared__ char sm[];
    __shared__ int s_g[BM2];

    const int b   = blockIdx.y;
    const int m0  = blockIdx.x * BM2;
    const int tid = threadIdx.x;
    const int w   = tid >> 5;
    const int wm  = w >> 2;          // 0..1 -> rows wm*32
    const int wn  = w & 3;           // 0..3 -> cols wn*64

    if (tid < BM2) s_g[tid] = b * N_ + g_down_idx[b * ND_ + m0 + tid];
    __syncthreads();

    const int ar = tid >> 2;         // 0..63
    const int ah = (tid & 3) * 8;    // 0,8,16,24
    const int g  = s_g[ar];

    wmma::fragment<wmma::accumulator, 16, 16, 16, float> acc[2][4];
#pragma unroll
    for (int i = 0; i < 2; ++i)
#pragma unroll
        for (int j = 0; j < 4; ++j) wmma::fill_fragment(acc[i][j], 0.0f);

    auto copyB = [&](int c, int s){
        const int k0 = c * 32;
        __nv_bfloat16* Bh = (__nv_bfloat16*)(sm + OFF_BHI(s));
        __nv_bfloat16* Bl = (__nv_bfloat16*)(sm + OFF_BLO(s));
#pragma unroll
        for (int q = 0; q < 4; ++q){
            const int i = tid + q * 256;
            const int row = i >> 5;
            const int col = (i & 31) * 8;
            cpa16(Bh + row * LDB2 + col, g_Whi + (size_t)(k0 + row) * H_ + col);
            cpa16(Bl + row * LDB2 + col, g_Wlo + (size_t)(k0 + row) * H_ + col);
        }
        asm volatile("cp.async.commit_group;");
    };
    auto storeA = [&](const float* xs, int s){
        unsigned hw[4], lw[4];
#pragma unroll
        for (int q = 0; q < 4; ++q){
            __nv_bfloat16 h0 = __float2bfloat16(xs[2*q]);
            __nv_bfloat16 h1 = __float2bfloat16(xs[2*q+1]);
            __nv_bfloat16 l0 = __float2bfloat16(xs[2*q]   - __bfloat162float(h0));
            __nv_bfloat16 l1 = __float2bfloat16(xs[2*q+1] - __bfloat162float(h1));
            __nv_bfloat162 hp2 = __nv_bfloat162(h0, h1);
            __nv_bfloat162 lp2 = __nv_bfloat162(l0, l1);
            hw[q] = *(unsigned*)&hp2;
            lw[q] = *(unsigned*)&lp2;
        }
        *(uint4*)((__nv_bfloat16*)(sm + OFF_AHI(s)) + ar * LDA2 + ah) =
            make_uint4(hw[0], hw[1], hw[2], hw[3]);
        *(uint4*)((__nv_bfloat16*)(sm + OFF_ALO(s)) + ar * LDA2 + ah) =
            make_uint4(lw[0], lw[1], lw[2], lw[3]);
    };

    float xs[8], xs2[8];
    loadA_regs(xs, hh, sl, sc, g, 0, ah);
    copyB(0, 0);

    for (int c = 0; c < 9; ++c){
        const int s = c & 1;
        if (c < 8){
            loadA_regs(xs2, hh, sl, sc, g, c + 1, ah);
            copyB(c + 1, s ^ 1);
        }
        storeA(xs, s);
        if (c < 8) asm volatile("cp.async.wait_group 1;");
        else       asm volatile("cp.async.wait_group 0;");
        __syncthreads();

        const __nv_bfloat16* Ah = (const __nv_bfloat16*)(sm + OFF_AHI(s));
        const __nv_bfloat16* Al = (const __nv_bfloat16*)(sm + OFF_ALO(s));
        const __nv_bfloat16* Bh = (const __nv_bfloat16*)(sm + OFF_BHI(s));
        const __nv_bfloat16* Bl = (const __nv_bfloat16*)(sm + OFF_BLO(s));
        // chunk 8 holds only k=256..259 (first k16 step); kt=1 is all zeros
        const int ktmax = (c == 8) ? 1 : 2;
#pragma unroll
        for (int kt = 0; kt < 2; ++kt){
            if (kt >= ktmax) break;
            const int ks = kt * 16;
            wmma::fragment<wmma::matrix_a, 16, 16, 16, __nv_bfloat16, wmma::row_major> fa_hi[2], fa_lo[2];
#pragma unroll
            for (int i = 0; i < 2; ++i){
                wmma::load_matrix_sync(fa_hi[i], Ah + (wm*32 + i*16) * LDA2 + ks, LDA2);
                wmma::load_matrix_sync(fa_lo[i], Al + (wm*32 + i*16) * LDA2 + ks, LDA2);
            }
#pragma unroll
            for (int j = 0; j < 4; ++j){
                wmma::fragment<wmma::matrix_b, 16, 16, 16, __nv_bfloat16, wmma::row_major> fb_hi, fb_lo;
                wmma::load_matrix_sync(fb_hi, Bh + ks * LDB2 + wn*64 + j*16, LDB2);
                wmma::load_matrix_sync(fb_lo, Bl + ks * LDB2 + wn*64 + j*16, LDB2);
#pragma unroll
                for (int i = 0; i < 2; ++i){
                    wmma::mma_sync(acc[i][j], fa_hi[i], fb_hi, acc[i][j]);
                    wmma::mma_sync(acc[i][j], fa_hi[i], fb_lo, acc[i][j]);
                    wmma::mma_sync(acc[i][j], fa_lo[i], fb_hi, acc[i][j]);
                }
            }
        }
        __syncthreads();
#pragma unroll
        for (int q = 0; q < 8; ++q) xs[q] = xs2[q];
    }

#pragma unroll
    for (int i = 0; i < 2; ++i){
        const int row = m0 + wm * 32 + i * 16;
#pragma unroll
        for (int j = 0; j < 4; ++j){
            const int col = wn * 64 + j * 16;
            wmma::store_matrix_sync(
                g_feat + ((size_t)b * ND_ + row) * H_ + col,
                acc[i][j], H_, wmma::mem_row_major);
        }
    }
}

// ---------------- K6: gather-max (+bias) into output ----------------
__global__ void k_gather(float* __restrict__ out, const float* __restrict__ bias){
    const int wid = threadIdx.x >> 5, lane = threadIdx.x & 31;
    const int row = blockIdx.x * 8 + wid;
    float* op = out + (size_t)row * H_;
    const int c0 = lane * 4;
    const float4 z = make_float4(0.f, 0.f, 0.f, 0.f);
    const int deg = g_deg[row];
    if (!g_isup[row] || deg == 0){
        *(float4*)(op + c0) = z;
        *(float4*)(op + c0 + 128) = z;
        return;
    }
    const int off = g_off[row];
    const float NI = __int_as_float(0xff800000);
    float4 a = make_float4(NI, NI, NI, NI), bq = a;
    for (int e = 0; e < deg; ++e){
        const float* fp = g_feat + (size_t)g_src[off + e] * H_;
        float4 u = *(const float4*)(fp + c0);
        float4 v = *(const float4*)(fp + c0 + 128);
        a.x = fmaxf(a.x, u.x); a.y = fmaxf(a.y, u.y);
        a.z = fmaxf(a.z, u.z); a.w = fmaxf(a.w, u.w);
        bq.x = fmaxf(bq.x, v.x); bq.y = fmaxf(bq.y, v.y);
        bq.z = fmaxf(bq.z, v.z); bq.w = fmaxf(bq.w, v.w);
    }
    const float4 ba = *(const float4*)(bias + c0);
    const float4 bb = *(const float4*)(bias + c0 + 128);
    a.x += ba.x; a.y += ba.y; a.z += ba.z; a.w += ba.w;
    bq.x += bb.x; bq.y += bb.y; bq.z += bb.z; bq.w += bb.w;
    *(float4*)(op + c0) = a;
    *(float4*)(op + c0 + 128) = bq;
}

// ------------------------------- launch ------------------------------------
extern "C" void kernel_launch(void* const* d_in, const int* in_sizes, int n_in,
                              void* d_out, int out_size){
    const float* hh = (const float*)d_in[0];
    const float* sl = (const float*)d_in[1];
    const float* sc = (const float*)d_in[2];
    const float* W  = (const float*)d_in[3];
    const float* bb = (const float*)d_in[4];
    (void)in_sizes; (void)n_in;

    cudaFuncSetAttribute(k_gemm_tc, cudaFuncAttributeMaxDynamicSharedMemorySize, SMEM_G);

    k_wsplit<<<(KP_*H_ + 255)/256, 256>>>(W);                       // 0
    k_select<<<B_, 1024>>>(sc, (float*)d_out, (long long)out_size); // 1

    // knn first: 256 CTAs, all resident wave-1, triggers PDL immediately
    dim3 gknn(ND_ / (256 * CHK), B_, KSL);                           // (8,8,4)
    k_knn_part<<<gknn, 256>>>(sl);                                   // 2

    // gemm launched with programmatic serialization: starts once all knn
    // CTAs have executed griddepcontrol.launch_dependents -> true overlap.
    {
        cudaLaunchConfig_t cfg = {};
        cfg.gridDim  = dim3(ND_ / BM2, B_, 1);
        cfg.blockDim = dim3(256, 1, 1);
        cfg.dynamicSmemBytes = SMEM_G;
        cfg.stream = 0;
        cudaLaunchAttribute at[1];
        at[0].id = cudaLaunchAttributeProgrammaticStreamSerialization;
        at[0].val.programmaticStreamSerializationAllowed = 1;
        cfg.attrs = at;
        cfg.numAttrs = 1;
        cudaLaunchKernelEx(&cfg, k_gemm_tc, hh, sl, sc);             // 3 (profiled)
    }

    k_knn_merge<<<(B_*ND_ + 255)/256, 256>>>();                      // 4
    k_scan<<<B_, 1024>>>();                                          // 5
    k_fill<<<(B_*ND_*M_ + 255)/256, 256>>>();                        // 6
    k_gather<<<B_*N_/8, 256>>>((float*)d_out, bb);                   // 7
}

// round 16
// speedup vs baseline: 1.1598x; 1.0199x over previous
#include <cuda_runtime.h>
#include <cuda_bf16.h>
#include <mma.h>
#include <cstdint>

using namespace nvcuda;

#define B_  8
#define N_  8192
#define H_  256
#define KD_ 260            // H + 4
#define KP_ 288            // K padded to 9*32
#define NU_ 2048
#define ND_ 6144
#define M_  5
#define EPG (ND_*M_)       // edges per graph = 30720
#define KSL 4              // KNN candidate slices
#define NSL (NU_/KSL)      // 512 candidates per slice
#define BM2 64             // GEMM M tile
#define GB_ (ND_/BM2*B_)   // gemm blocks = 768
#define KB_ ((ND_/256)*B_*KSL) // knn blocks = 24*8*4 = 768
#define LDA2 40
#define LDB2 264
#define OFF_AHI(s) ((s)*5120)
#define OFF_ALO(s) (10240 + (s)*5120)
#define OFF_BHI(s) (20480 + (s)*16896)
#define OFF_BLO(s) (54272 + (s)*16896)
#define SMEM_G 88064

// ---------------- device scratch ----------------
__device__ int  g_up_idx[B_*NU_];
__device__ int  g_down_idx[B_*ND_];
__device__ int  g_dst[B_*ND_*M_];
__device__ unsigned char g_isup[B_*N_];
__device__ int  g_deg[B_*N_];
__device__ int  g_off[B_*N_];
__device__ int  g_cur[B_*N_];
__device__ int  g_src[B_*ND_*M_];
__device__ float g_feat[(size_t)B_*ND_*H_];
__device__ __nv_bfloat16 g_Whi[KP_*H_];
__device__ __nv_bfloat16 g_Wlo[KP_*H_];
__device__ float g_pd[(size_t)B_*ND_*KSL*M_];
__device__ int   g_pi[(size_t)B_*ND_*KSL*M_];

__device__ __forceinline__ unsigned enc_f(float f){
    unsigned u = __float_as_uint(f);
    return (u & 0x80000000u) ? ~u : (u | 0x80000000u);
}
__device__ __forceinline__ void cpa16(void* dst, const void* src){
    unsigned d = (unsigned)__cvta_generic_to_shared(dst);
    asm volatile("cp.async.cg.shared.global [%0], [%1], 16;" :: "r"(d), "l"(src));
}

__device__ __forceinline__ int block_scan_excl(int val, int* s_warp, int tid){
    const int lane = tid & 31, wid = tid >> 5;
    int inc = val;
#pragma unroll
    for (int o = 1; o < 32; o <<= 1){
        int v = __shfl_up_sync(0xFFFFFFFFu, inc, o);
        if (lane >= o) inc += v;
    }
    if (lane == 31) s_warp[wid] = inc;
    __syncthreads();
    if (wid == 0){
        int w = (lane < 32) ? s_warp[lane] : 0;
#pragma unroll
        for (int o = 1; o < 32; o <<= 1){
            int v = __shfl_up_sync(0xFFFFFFFFu, w, o);
            if (lane >= o) w += v;
        }
        s_warp[lane] = w;
    }
    __syncthreads();
    int base = (wid > 0) ? s_warp[wid - 1] : 0;
    return base + inc - val;
}

// ---------------- K-1: zero degree array (slot 0) ----------------
__global__ void k_zero(){
    g_deg[blockIdx.x * 256 + threadIdx.x] = 0;
}

// ---------------- K0: W split into hi/lo bf16 ----------------
__global__ void k_wsplit(const float* __restrict__ W){
    const int idx = blockIdx.x * 256 + threadIdx.x;
    if (idx >= KP_ * H_) return;
    const int k = idx / H_, n = idx % H_;
    const float w = (k < KD_) ? W[k * H_ + n] : 0.0f;
    const __nv_bfloat16 hi = __float2bfloat16(w);
    const __nv_bfloat16 lo = __float2bfloat16(w - __bfloat162float(hi));
    g_Whi[idx] = hi;
    g_Wlo[idx] = lo;
}

// ---------------- K1: top-25% selection ----------------
__global__ void k_select(const float* __restrict__ scores,
                         float* __restrict__ d_out, long long out_size){
    __shared__ unsigned s_enc[N_];
    __shared__ int s_warp[32];
    __shared__ int s_hist[256];
    __shared__ int s_bcast[2];
    const int b = blockIdx.x, tid = threadIdx.x;

    const float* sc = scores + (long long)b * N_;
    for (int i = tid; i < N_; i += 1024) s_enc[i] = enc_f(sc[i]);
    __syncthreads();

    unsigned prefix = 0, known = 0;
    int k = NU_;
    for (int lvl = 3; lvl >= 0; --lvl){
        if (tid < 256) s_hist[tid] = 0;
        __syncthreads();
        const int sh = lvl * 8;
        for (int i = tid; i < N_; i += 1024){
            unsigned e = s_enc[i];
            if ((e & known) == prefix) atomicAdd(&s_hist[(e >> sh) & 255], 1);
        }
        __syncthreads();
        if (tid == 0){
            int kk = k, bin = 255;
            while (bin > 0 && kk > s_hist[bin]) { kk -= s_hist[bin]; --bin; }
            s_bcast[0] = bin; s_bcast[1] = kk;
        }
        __syncthreads();
        prefix |= ((unsigned)s_bcast[0]) << sh;
        known  |= 0xFFu << sh;
        k = s_bcast[1];
        __syncthreads();
    }
    const unsigned T = prefix;

    if (tid == 0) s_bcast[0] = 0;
    __syncthreads();
    {
        int loc = 0;
        for (int i = tid; i < N_; i += 1024) if (s_enc[i] > T) loc++;
        atomicAdd(&s_bcast[0], loc);
    }
    __syncthreads();
    const int need_eq = NU_ - s_bcast[0];
    __syncthreads();

    const int base = tid * 8;
    int eqc = 0;
#pragma unroll
    for (int e = 0; e < 8; ++e) eqc += (s_enc[base + e] == T);
    int eqbase = block_scan_excl(eqc, s_warp, tid);
    __syncthreads();

    unsigned mbits = 0; int upc = 0;
    {
        int ec = eqbase;
#pragma unroll
        for (int e = 0; e < 8; ++e){
            unsigned v = s_enc[base + e];
            bool msk;
            if (v > T) msk = true;
            else if (v == T) { msk = (ec < need_eq); ec++; }
            else msk = false;
            if (msk) { mbits |= (1u << e); upc++; }
        }
    }
    int upbase = block_scan_excl(upc, s_warp, tid);

    const long long BNH = (long long)B_ * N_ * H_;
    const bool wf = (out_size == BNH + (long long)B_ * N_);
    const bool wb = (out_size == BNH + ((long long)B_ * N_) / 4);
    int up = upbase;
#pragma unroll
    for (int e = 0; e < 8; ++e){
        const int i = base + e;
        const bool msk = (mbits >> e) & 1;
        if (msk) { g_up_idx[b * NU_ + up] = i; up++; }
        else       g_down_idx[b * ND_ + (i - up)] = i;
        g_isup[b * N_ + i] = msk ? 1 : 0;
        if (wf)      d_out[BNH + (long long)b * N_ + i] = msk ? 1.0f : 0.0f;
        else if (wb) ((unsigned char*)d_out)[BNH * 4 + (long long)b * N_ + i] = msk ? 1 : 0;
    }
}

// -------- top-5 helpers --------
struct Top5 { float d0,d1,d2,d3,d4; int i0,i1,i2,i3,i4; };
__device__ __forceinline__ void top5_init(Top5& t){
    const float INF = __int_as_float(0x7f800000);
    t.d0=t.d1=t.d2=t.d3=t.d4=INF; t.i0=t.i1=t.i2=t.i3=t.i4=0;
}
__device__ __forceinline__ void top5_ins(Top5& t, float d, int j){
    if (d < t.d4){
        if (d < t.d3){ t.d4=t.d3; t.i4=t.i3;
            if (d < t.d2){ t.d3=t.d2; t.i3=t.i2;
                if (d < t.d1){ t.d2=t.d1; t.i2=t.i1;
                    if (d < t.d0){ t.d1=t.d0; t.i1=t.i0; t.d0=d; t.i0=j; }
                    else        { t.d1=d;  t.i1=j; }
                } else { t.d2=d; t.i2=j; }
            } else { t.d3=d; t.i3=j; }
        } else { t.d4=d; t.i4=j; }
    }
}

// -------- bodies for the fused kernel --------
__device__ __forceinline__ void loadA_regs(float* xs, const float* __restrict__ hh,
                                           const float* __restrict__ sl,
                                           const float* __restrict__ sc,
                                           int g, int c, int ah){
    if (c < 8){
        const float4* hp = (const float4*)(hh + (size_t)g * H_ + c * 32 + ah);
        float4 f0 = hp[0], f1 = hp[1];
        xs[0]=f0.x; xs[1]=f0.y; xs[2]=f0.z; xs[3]=f0.w;
        xs[4]=f1.x; xs[5]=f1.y; xs[6]=f1.z; xs[7]=f1.w;
    } else {
#pragma unroll
        for (int q = 0; q < 8; ++q) xs[q] = 0.0f;
        if (ah == 0){
            xs[0] = sl[(size_t)g * 3];
            xs[1] = sl[(size_t)g * 3 + 1];
            xs[2] = sl[(size_t)g * 3 + 2];
            xs[3] = sc[g];
        }
    }
}

__device__ void gemm_body(char* sm, int gblk,
                          const float* __restrict__ hh,
                          const float* __restrict__ sl,
                          const float* __restrict__ sc){
    __shared__ int s_g[BM2];
    const int b   = gblk / (ND_ / BM2);
    const int m0  = (gblk % (ND_ / BM2)) * BM2;
    const int tid = threadIdx.x;
    const int w   = tid >> 5;
    const int wm  = w >> 2;
    const int wn  = w & 3;

    if (tid < BM2) s_g[tid] = b * N_ + g_down_idx[b * ND_ + m0 + tid];
    __syncthreads();

    const int ar = tid >> 2;
    const int ah = (tid & 3) * 8;
    const int g  = s_g[ar];

    wmma::fragment<wmma::accumulator, 16, 16, 16, float> acc[2][4];
#pragma unroll
    for (int i = 0; i < 2; ++i)
#pragma unroll
        for (int j = 0; j < 4; ++j) wmma::fill_fragment(acc[i][j], 0.0f);

    auto copyB = [&](int c, int s){
        const int k0 = c * 32;
        __nv_bfloat16* Bh = (__nv_bfloat16*)(sm + OFF_BHI(s));
        __nv_bfloat16* Bl = (__nv_bfloat16*)(sm + OFF_BLO(s));
#pragma unroll
        for (int q = 0; q < 4; ++q){
            const int i = tid + q * 256;
            const int row = i >> 5;
            const int col = (i & 31) * 8;
            cpa16(Bh + row * LDB2 + col, g_Whi + (size_t)(k0 + row) * H_ + col);
            cpa16(Bl + row * LDB2 + col, g_Wlo + (size_t)(k0 + row) * H_ + col);
        }
        asm volatile("cp.async.commit_group;");
    };
    auto storeA = [&](const float* xs, int s){
        unsigned hw[4], lw[4];
#pragma unroll
        for (int q = 0; q < 4; ++q){
            __nv_bfloat16 h0 = __float2bfloat16(xs[2*q]);
            __nv_bfloat16 h1 = __float2bfloat16(xs[2*q+1]);
            __nv_bfloat16 l0 = __float2bfloat16(xs[2*q]   - __bfloat162float(h0));
            __nv_bfloat16 l1 = __float2bfloat16(xs[2*q+1] - __bfloat162float(h1));
            __nv_bfloat162 hp2 = __nv_bfloat162(h0, h1);
            __nv_bfloat162 lp2 = __nv_bfloat162(l0, l1);
            hw[q] = *(unsigned*)&hp2;
            lw[q] = *(unsigned*)&lp2;
        }
        *(uint4*)((__nv_bfloat16*)(sm + OFF_AHI(s)) + ar * LDA2 + ah) =
            make_uint4(hw[0], hw[1], hw[2], hw[3]);
        *(uint4*)((__nv_bfloat16*)(sm + OFF_ALO(s)) + ar * LDA2 + ah) =
            make_uint4(lw[0], lw[1], lw[2], lw[3]);
    };

    float xs[8], xs2[8];
    loadA_regs(xs, hh, sl, sc, g, 0, ah);
    copyB(0, 0);

    for (int c = 0; c < 9; ++c){
        const int s = c & 1;
        if (c < 8){
            loadA_regs(xs2, hh, sl, sc, g, c + 1, ah);
            copyB(c + 1, s ^ 1);
        }
        storeA(xs, s);
        if (c < 8) asm volatile("cp.async.wait_group 1;");
        else       asm volatile("cp.async.wait_group 0;");
        __syncthreads();

        const __nv_bfloat16* Ah = (const __nv_bfloat16*)(sm + OFF_AHI(s));
        const __nv_bfloat16* Al = (const __nv_bfloat16*)(sm + OFF_ALO(s));
        const __nv_bfloat16* Bh = (const __nv_bfloat16*)(sm + OFF_BHI(s));
        const __nv_bfloat16* Bl = (const __nv_bfloat16*)(sm + OFF_BLO(s));
        const int ktmax = (c == 8) ? 1 : 2;   // tail trim: k>=260 is zero
#pragma unroll
        for (int kt = 0; kt < 2; ++kt){
            if (kt >= ktmax) break;
            const int ks = kt * 16;
            wmma::fragment<wmma::matrix_a, 16, 16, 16, __nv_bfloat16, wmma::row_major> fa_hi[2], fa_lo[2];
#pragma unroll
            for (int i = 0; i < 2; ++i){
                wmma::load_matrix_sync(fa_hi[i], Ah + (wm*32 + i*16) * LDA2 + ks, LDA2);
                wmma::load_matrix_sync(fa_lo[i], Al + (wm*32 + i*16) * LDA2 + ks, LDA2);
            }
#pragma unroll
            for (int j = 0; j < 4; ++j){
                wmma::fragment<wmma::matrix_b, 16, 16, 16, __nv_bfloat16, wmma::row_major> fb_hi, fb_lo;
                wmma::load_matrix_sync(fb_hi, Bh + ks * LDB2 + wn*64 + j*16, LDB2);
                wmma::load_matrix_sync(fb_lo, Bl + ks * LDB2 + wn*64 + j*16, LDB2);
#pragma unroll
                for (int i = 0; i < 2; ++i){
                    wmma::mma_sync(acc[i][j], fa_hi[i], fb_hi, acc[i][j]);
                    wmma::mma_sync(acc[i][j], fa_hi[i], fb_lo, acc[i][j]);
                    wmma::mma_sync(acc[i][j], fa_lo[i], fb_hi, acc[i][j]);
                }
            }
        }
        __syncthreads();
#pragma unroll
        for (int q = 0; q < 8; ++q) xs[q] = xs2[q];
    }

#pragma unroll
    for (int i = 0; i < 2; ++i){
        const int row = m0 + wm * 32 + i * 16;
#pragma unroll
        for (int j = 0; j < 4; ++j){
            const int col = wn * 64 + j * 16;
            wmma::store_matrix_sync(
                g_feat + ((size_t)b * ND_ + row) * H_ + col,
                acc[i][j], H_, wmma::mem_row_major);
        }
    }
}

__device__ void knn_body(char* sm, int kblk, const float* __restrict__ s_l){
    float4* su = (float4*)sm;            // NSL * 16B = 8 KB of the dyn smem
    const int kx  = kblk % (ND_ / 256);  // 0..23
    const int rem = kblk / (ND_ / 256);
    const int b   = rem % B_;
    const int sl  = rem / B_;            // 0..KSL-1
    const int tid = threadIdx.x;

    for (int j = tid; j < NSL; j += 256){
        int u = g_up_idx[b * NU_ + sl * NSL + j];
        long long p = ((long long)b * N_ + u) * 3;
        su[j] = make_float4(s_l[p], s_l[p+1], s_l[p+2], __int_as_float(b * N_ + u));
    }
    __syncthreads();

    const int dl = kx * 256 + tid;
    const int dn = g_down_idx[b * ND_ + dl];
    long long p = ((long long)b * N_ + dn) * 3;
    const float x = s_l[p], y = s_l[p+1], z = s_l[p+2];

    Top5 t; top5_init(t);
    for (int j0 = 0; j0 < NSL; j0 += 4){
        const float4 u0 = su[j0], u1 = su[j0+1], u2 = su[j0+2], u3 = su[j0+3];
        float dx0 = x-u0.x, dy0 = y-u0.y, dz0 = z-u0.z;
        float dx1 = x-u1.x, dy1 = y-u1.y, dz1 = z-u1.z;
        float dx2 = x-u2.x, dy2 = y-u2.y, dz2 = z-u2.z;
        float dx3 = x-u3.x, dy3 = y-u3.y, dz3 = z-u3.z;
        float dA = dx0*dx0 + dy0*dy0 + dz0*dz0;
        float dB = dx1*dx1 + dy1*dy1 + dz1*dz1;
        float dC = dx2*dx2 + dy2*dy2 + dz2*dz2;
        float dD = dx3*dx3 + dy3*dy3 + dz3*dz3;
        top5_ins(t, dA, j0);
        top5_ins(t, dB, j0+1);
        top5_ins(t, dC, j0+2);
        top5_ins(t, dD, j0+3);
    }
    const size_t base = (((size_t)b * ND_ + dl) * KSL + sl) * M_;
    g_pd[base+0]=t.d0; g_pd[base+1]=t.d1; g_pd[base+2]=t.d2;
    g_pd[base+3]=t.d3; g_pd[base+4]=t.d4;
    g_pi[base+0]=__float_as_int(su[t.i0].w);
    g_pi[base+1]=__float_as_int(su[t.i1].w);
    g_pi[base+2]=__float_as_int(su[t.i2].w);
    g_pi[base+3]=__float_as_int(su[t.i3].w);
    g_pi[base+4]=__float_as_int(su[t.i4].w);
}

// -------- K2: FUSED gemm + knn (grid union, interleaved bids) --------
__global__ void __launch_bounds__(256, 2)
k_fused(const float* __restrict__ hh, const float* __restrict__ sl,
        const float* __restrict__ sc){
    extern __shared__ char sm[];
    const int bid = blockIdx.x;
    if ((bid & 1) == 0) gemm_body(sm, bid >> 1, hh, sl, sc);
    else                knn_body(sm, bid >> 1, sl);
}

// -------- K2b: KNN phase 2 — 4-way merge of sorted 5-lists + degrees --------
__global__ void k_knn_merge(){
    const int pt = blockIdx.x * 256 + threadIdx.x;
    if (pt >= B_ * ND_) return;
    const size_t b0 = (size_t)pt * KSL * M_;
    float ld[KSL][5]; int li[KSL][5];
#pragma unroll
    for (int s = 0; s < KSL; ++s)
#pragma unroll
        for (int q = 0; q < 5; ++q){
            ld[s][q] = g_pd[b0 + s*5 + q];
            li[s][q] = g_pi[b0 + s*5 + q];
        }
    int hp[KSL];
#pragma unroll
    for (int s = 0; s < KSL; ++s) hp[s] = 0;
    int* dst = g_dst + (size_t)pt * M_;
    const float INF = __int_as_float(0x7f800000);
#pragma unroll
    for (int k = 0; k < 5; ++k){
        int bs = 0; float bd = INF;
#pragma unroll
        for (int s = 0; s < KSL; ++s){
            float v = (hp[s] < 5) ? ld[s][hp[s]] : INF;
            if (v < bd){ bd = v; bs = s; }
        }
        int e = li[bs][hp[bs]];
        hp[bs]++;
        dst[k] = e;
        atomicAdd(&g_deg[e], 1);
    }
}

// -------- K3: per-graph exclusive scan --------
__global__ void k_scan(){
    __shared__ int s_warp[32];
    const int b = blockIdx.x, tid = threadIdx.x;
    const int base = b * N_ + tid * 8;
    int d[8]; int s = 0;
#pragma unroll
    for (int i = 0; i < 8; ++i){ d[i] = g_deg[base + i]; s += d[i]; }
    int run = block_scan_excl(s, s_warp, tid) + b * EPG;
#pragma unroll
    for (int i = 0; i < 8; ++i){
        g_off[base + i] = run;
        g_cur[base + i] = run;
        run += d[i];
    }
}

// ---------------- K4: CSR fill ----------------
__global__ void k_fill(){
    const int e = blockIdx.x * 256 + threadIdx.x;
    if (e >= B_ * ND_ * M_) return;
    const int dst = g_dst[e];
    const int pos = atomicAdd(&g_cur[dst], 1);
    g_src[pos] = e / M_;
}

// ---------------- K6: gather-max (+bias) into output ----------------
__global__ void k_gather(float* __restrict__ out, const float* __restrict__ bias){
    const int wid = threadIdx.x >> 5, lane = threadIdx.x & 31;
    const int row = blockIdx.x * 8 + wid;
    float* op = out + (size_t)row * H_;
    const int c0 = lane * 4;
    const float4 z = make_float4(0.f, 0.f, 0.f, 0.f);
    const int deg = g_deg[row];
    if (!g_isup[row] || deg == 0){
        *(float4*)(op + c0) = z;
        *(float4*)(op + c0 + 128) = z;
        return;
    }
    const int off = g_off[row];
    const float NI = __int_as_float(0xff800000);
    float4 a = make_float4(NI, NI, NI, NI), bq = a;
    for (int e = 0; e < deg; ++e){
        const float* fp = g_feat + (size_t)g_src[off + e] * H_;
        float4 u = *(const float4*)(fp + c0);
        float4 v = *(const float4*)(fp + c0 + 128);
        a.x = fmaxf(a.x, u.x); a.y = fmaxf(a.y, u.y);
        a.z = fmaxf(a.z, u.z); a.w = fmaxf(a.w, u.w);
        bq.x = fmaxf(bq.x, v.x); bq.y = fmaxf(bq.y, v.y);
        bq.z = fmaxf(bq.z, v.z); bq.w = fmaxf(bq.w, v.w);
    }
    const float4 ba = *(const float4*)(bias + c0);
    const float4 bb = *(const float4*)(bias + c0 + 128);
    a.x += ba.x; a.y += ba.y; a.z += ba.z; a.w += ba.w;
    bq.x += bb.x; bq.y += bb.y; bq.z += bb.z; bq.w += bb.w;
    *(float4*)(op + c0) = a;
    *(float4*)(op + c0 + 128) = bq;
}

// ------------------------------- launch ------------------------------------
extern "C" void kernel_launch(void* const* d_in, const int* in_sizes, int n_in,
                              void* d_out, int out_size){
    const float* hh = (const float*)d_in[0];
    const float* sl = (const float*)d_in[1];
    const float* sc = (const float*)d_in[2];
    const float* W  = (const float*)d_in[3];
    const float* bb = (const float*)d_in[4];
    (void)in_sizes; (void)n_in;

    cudaFuncSetAttribute(k_fused, cudaFuncAttributeMaxDynamicSharedMemorySize, SMEM_G);

    k_zero<<<B_*N_/256, 256>>>();                                    // 0
    k_wsplit<<<(KP_*H_ + 255)/256, 256>>>(W);                        // 1
    k_select<<<B_, 1024>>>(sc, (float*)d_out, (long long)out_size);  // 2
    k_fused<<<GB_ + KB_, 256, SMEM_G>>>(hh, sl, sc);                 // 3 (profiled)
    k_knn_merge<<<(B_*ND_ + 255)/256, 256>>>();                       // 4
    k_scan<<<B_, 1024>>>();                                           // 5
    k_fill<<<(B_*ND_*M_ + 255)/256, 256>>>();                         // 6
    k_gather<<<B_*N_/8, 256>>>((float*)d_out, bb);                    // 7
}